// round 2
// baseline (speedup 1.0000x reference)
#include <cuda_runtime.h>
#include <cstdint>

#define NN 50000
#define DD 300
#define EE 400000
#define LL 5
#define CC 128
#define NGR 256
#define BN_EPS 1e-5f

typedef unsigned long long u64;

// ---------------- device scratch (no allocs allowed) ----------------
__device__ float g_bufA[NN * DD];
__device__ float g_bufB[NN * DD];
__device__ float g_bufT[NN * DD];
__device__ float g_pooled[(LL + 1) * NGR * DD];
__device__ float g_counts[NGR];
__device__ float g_stats[8 * DD];   // [0]=sum1 [1]=sq1 [2]=sum2 [3]=sq2 [4]=scale1 [5]=shift1 [6]=scale2 [7]=shift2

// ---------------- f32x2 FMA (FFMA2: 2x fp32 throughput, PTX-only) ----------------
__device__ __forceinline__ void ffma2(u64& d, u64 a, u64 b) {
    asm volatile("fma.rn.f32x2 %0, %1, %2, %0;" : "+l"(d) : "l"(a), "l"(b));
}
__device__ __forceinline__ u64 dup_f32(unsigned u) {
    return (u64)u | ((u64)u << 32);
}

// ---------------- GEMM: out[M,300] = A[M,300] @ W[300,300] + bias ----------------
// Fused epilogue: per-column sum / sumsq accumulated into gsum/gsq (pre-zeroed).
// Tiles: 128x128x16, 256 threads, 8x8 microtile as 8 rows x 4 f32x2 column-pairs.
__global__ __launch_bounds__(256, 2)
void gemm_bias_stats(const float* __restrict__ A, const float* __restrict__ W,
                     const float* __restrict__ bias, float* __restrict__ out,
                     float* __restrict__ gsum, float* __restrict__ gsq, int M)
{
    __shared__ __align__(16) u64   As[16][128];   // A transposed, each value duplicated as (a,a)
    __shared__ __align__(16) float Bs[16][128];
    __shared__ float ssum[128];
    __shared__ float ssq[128];

    const int tid = threadIdx.x;
    const int tx = tid & 15, ty = tid >> 4;
    const int m0 = blockIdx.y * 128;
    const int n0 = blockIdx.x * 128;

    u64 acc[8][4];
#pragma unroll
    for (int i = 0; i < 8; i++)
#pragma unroll
        for (int j = 0; j < 4; j++) acc[i][j] = 0ull;

    const int KT = (DD + 15) / 16;  // 19 (last tile zero-padded)
    for (int kb = 0; kb < KT; kb++) {
        const int k0 = kb * 16;
        // load A tile -> As (transpose + duplicate)
#pragma unroll
        for (int j = 0; j < 2; j++) {
            int li = tid + 256 * j;        // 0..511
            int r = li >> 2;               // row in tile 0..127
            int kq = li & 3;               // which float4 of the 16 k's
            int m = m0 + r;
            int kk = k0 + kq * 4;
            float4 v = make_float4(0.f, 0.f, 0.f, 0.f);
            if (m < M && kk < DD)
                v = *reinterpret_cast<const float4*>(A + (size_t)m * DD + kk);
            As[kq * 4 + 0][r] = dup_f32(__float_as_uint(v.x));
            As[kq * 4 + 1][r] = dup_f32(__float_as_uint(v.y));
            As[kq * 4 + 2][r] = dup_f32(__float_as_uint(v.z));
            As[kq * 4 + 3][r] = dup_f32(__float_as_uint(v.w));
        }
        // load W tile -> Bs
#pragma unroll
        for (int j = 0; j < 2; j++) {
            int li = tid + 256 * j;
            int kr = li >> 5;              // 0..15
            int nq = li & 31;              // 0..31
            int kk = k0 + kr;
            int n = n0 + nq * 4;
            float4 v = make_float4(0.f, 0.f, 0.f, 0.f);
            if (kk < DD && n < DD)
                v = *reinterpret_cast<const float4*>(W + (size_t)kk * DD + n);
            *reinterpret_cast<float4*>(&Bs[kr][nq * 4]) = v;
        }
        __syncthreads();

#pragma unroll
        for (int k = 0; k < 16; k++) {
            const ulonglong2* pa = reinterpret_cast<const ulonglong2*>(&As[k][ty * 8]);
            ulonglong2 t0 = pa[0], t1 = pa[1], t2 = pa[2], t3 = pa[3];
            u64 a2[8] = { t0.x, t0.y, t1.x, t1.y, t2.x, t2.y, t3.x, t3.y };
            const ulonglong2* pb = reinterpret_cast<const ulonglong2*>(&Bs[k][tx * 8]);
            ulonglong2 s0 = pb[0], s1 = pb[1];
            u64 b2[4] = { s0.x, s0.y, s1.x, s1.y };
#pragma unroll
            for (int i = 0; i < 8; i++)
#pragma unroll
                for (int j = 0; j < 4; j++) ffma2(acc[i][j], a2[i], b2[j]);
        }
        __syncthreads();
    }

    // epilogue: bias add, store, per-thread column stats
    float csum[8], csq[8];
#pragma unroll
    for (int j = 0; j < 8; j++) { csum[j] = 0.f; csq[j] = 0.f; }

#pragma unroll
    for (int i = 0; i < 8; i++) {
        int m = m0 + ty * 8 + i;
        if (m >= M) continue;
#pragma unroll
        for (int j = 0; j < 4; j++) {
            int n = n0 + tx * 8 + 2 * j;
            if (n < DD) {
                u64 a = acc[i][j];
                float2 v;
                v.x = __uint_as_float((unsigned)(a & 0xffffffffull)) + __ldg(&bias[n]);
                v.y = __uint_as_float((unsigned)(a >> 32)) + __ldg(&bias[n + 1]);
                *reinterpret_cast<float2*>(out + (size_t)m * DD + n) = v;
                csum[2 * j]     += v.x; csq[2 * j]     += v.x * v.x;
                csum[2 * j + 1] += v.y; csq[2 * j + 1] += v.y * v.y;
            }
        }
    }

    if (tid < 128) { ssum[tid] = 0.f; ssq[tid] = 0.f; }
    __syncthreads();
#pragma unroll
    for (int j = 0; j < 8; j++) {
        int nl = tx * 8 + j;
        atomicAdd(&ssum[nl], csum[j]);
        atomicAdd(&ssq[nl], csq[j]);
    }
    __syncthreads();
    if (tid < 128) {
        int n = n0 + tid;
        if (n < DD) {
            atomicAdd(&gsum[n], ssum[tid]);
            atomicAdd(&gsq[n], ssq[tid]);
        }
    }
}

// ---------------- scatter-add: z[dst] += h[src] over edges (indices are int32!) ----------------
__global__ void scatter_add_kernel(const int* __restrict__ ei,
                                   const float* __restrict__ h,
                                   float* __restrict__ z)
{
    int w = blockIdx.x * blockDim.x + threadIdx.x;
    if (w >= EE * 75) return;
    int e = w / 75;
    int q = (w - e * 75) * 4;
    int s = ei[e];
    int d = ei[EE + e];
    float4 v = *reinterpret_cast<const float4*>(h + (size_t)s * DD + q);
    float* p = z + (size_t)d * DD + q;
    atomicAdd(p + 0, v.x);
    atomicAdd(p + 1, v.y);
    atomicAdd(p + 2, v.z);
    atomicAdd(p + 3, v.w);
}

// ---------------- BN prep: scale/shift per column from sums ----------------
__global__ void bn_prep_kernel(const float* __restrict__ gsum, const float* __restrict__ gsq,
                               const float* __restrict__ gamma, const float* __restrict__ beta,
                               float* __restrict__ scale, float* __restrict__ shift)
{
    int c = blockIdx.x * blockDim.x + threadIdx.x;
    if (c >= DD) return;
    const float invN = 1.0f / (float)NN;
    float mu = gsum[c] * invN;
    float var = gsq[c] * invN - mu * mu;
    float rs = rsqrtf(var + BN_EPS);
    float sc = rs * gamma[c];
    scale[c] = sc;
    shift[c] = beta[c] - mu * sc;
}

// ---------------- BN apply + ReLU (in place) ----------------
__global__ void bn_relu_kernel(float* __restrict__ t,
                               const float* __restrict__ scale,
                               const float* __restrict__ shift)
{
    int idx = blockIdx.x * blockDim.x + threadIdx.x;   // over NN*75 float4's
    if (idx >= NN * 75) return;
    int c = (idx % 75) * 4;
    float4 v = *reinterpret_cast<float4*>(t + (size_t)idx * 4);
    float4 r;
    r.x = fmaxf(v.x * __ldg(&scale[c + 0]) + __ldg(&shift[c + 0]), 0.f);
    r.y = fmaxf(v.y * __ldg(&scale[c + 1]) + __ldg(&shift[c + 1]), 0.f);
    r.z = fmaxf(v.z * __ldg(&scale[c + 2]) + __ldg(&shift[c + 2]), 0.f);
    r.w = fmaxf(v.w * __ldg(&scale[c + 3]) + __ldg(&shift[c + 3]), 0.f);
    *reinterpret_cast<float4*>(t + (size_t)idx * 4) = r;
}

// ---------------- per-graph pooling (batch is sorted int32: binary-search bounds) ----------------
__global__ void pool_kernel(const float* __restrict__ h,
                            const int* __restrict__ batch,
                            float* __restrict__ pooled,
                            float* __restrict__ counts)
{
    int g = blockIdx.x;
    int lo = 0, hi = NN;
    while (lo < hi) { int mid = (lo + hi) >> 1; if (batch[mid] < g) lo = mid + 1; else hi = mid; }
    int s = lo;
    lo = s; hi = NN;
    while (lo < hi) { int mid = (lo + hi) >> 1; if (batch[mid] < g + 1) lo = mid + 1; else hi = mid; }
    int e = lo;

    if (counts && threadIdx.x == 0 && blockIdx.y == 0) counts[g] = (float)(e - s);

    int c = blockIdx.y * 100 + threadIdx.x;
    if (threadIdx.x < 100) {
        float acc = 0.f;
        for (int n = s; n < e; n++) acc += h[(size_t)n * DD + c];
        pooled[(size_t)g * DD + c] = acc;
    }
}

// ---------------- readout heads ----------------
__global__ void head_kernel(const float* __restrict__ pooled,
                            const float* __restrict__ counts,
                            const float* __restrict__ fcW,
                            const float* __restrict__ fcb,
                            float* __restrict__ out)
{
    int g = blockIdx.x;
    int c = threadIdx.x;   // 128
    float inv = 1.0f / fmaxf(counts[g], 1.0f);
    float acc = 0.f;
#pragma unroll
    for (int i = 0; i <= LL; i++) {
        const float* p = pooled + ((size_t)i * NGR + g) * DD;
        const float* Wp = fcW + (size_t)i * DD * CC + c;
        float s = 0.f;
#pragma unroll 4
        for (int k = 0; k < DD; k++) s += __ldg(&p[k]) * __ldg(&Wp[(size_t)k * CC]);
        acc += s * inv + __ldg(&fcb[i * CC + c]);
    }
    out[(size_t)g * CC + c] = acc;
}

// ---------------- launch ----------------
extern "C" void kernel_launch(void* const* d_in, const int* in_sizes, int n_in,
                              void* d_out, int out_size)
{
    // Input index maps: insertion (dict) order vs alphabetical order, detected by in_sizes[0].
    // insertion: x, edge_index, batch, mlp_W1, mlp_b1, mlp_g1, mlp_be1, mlp_W2, mlp_b2, bn_g, bn_b, fc_W, fc_b
    // alpha:     batch, bn_b, bn_g, edge_index, fc_W, fc_b, mlp_W1, mlp_W2, mlp_b1, mlp_b2, mlp_be1, mlp_g1, x
    int ix, iei, ibatch, iW1, ib1, ig1, ibe1, iW2, ib2, ibng, ibnb, ifcW, ifcb;
    if (in_sizes[0] == NN) {  // alphabetical (batch first)
        ibatch = 0; ibnb = 1; ibng = 2; iei = 3; ifcW = 4; ifcb = 5;
        iW1 = 6; iW2 = 7; ib1 = 8; ib2 = 9; ibe1 = 10; ig1 = 11; ix = 12;
    } else {                  // insertion order
        ix = 0; iei = 1; ibatch = 2; iW1 = 3; ib1 = 4; ig1 = 5; ibe1 = 6;
        iW2 = 7; ib2 = 8; ibng = 9; ibnb = 10; ifcW = 11; ifcb = 12;
    }

    const float* x     = (const float*)d_in[ix];
    const int*   ei    = (const int*)d_in[iei];      // int32 (JAX x64 disabled)
    const int*   batch = (const int*)d_in[ibatch];   // int32
    const float* W1    = (const float*)d_in[iW1];
    const float* b1    = (const float*)d_in[ib1];
    const float* g1    = (const float*)d_in[ig1];
    const float* be1   = (const float*)d_in[ibe1];
    const float* W2    = (const float*)d_in[iW2];
    const float* b2    = (const float*)d_in[ib2];
    const float* bng   = (const float*)d_in[ibng];
    const float* bnb   = (const float*)d_in[ibnb];
    const float* fcW   = (const float*)d_in[ifcW];
    const float* fcb   = (const float*)d_in[ifcb];
    float* out = (float*)d_out;

    float *bufA, *bufB, *bufT, *pooled, *counts, *stats;
    cudaGetSymbolAddress((void**)&bufA,   g_bufA);
    cudaGetSymbolAddress((void**)&bufB,   g_bufB);
    cudaGetSymbolAddress((void**)&bufT,   g_bufT);
    cudaGetSymbolAddress((void**)&pooled, g_pooled);
    cudaGetSymbolAddress((void**)&counts, g_counts);
    cudaGetSymbolAddress((void**)&stats,  g_stats);

    dim3 pg(NGR, 3);
    pool_kernel<<<pg, 128>>>(x, batch, pooled, counts);

    const float* hcur = x;
    float* zb[2] = { bufA, bufB };
    const dim3 gemm_grid(3, (NN + 127) / 128);
    const int scat_blocks = (EE * 75 + 255) / 256;
    const int bn_blocks = (NN * 75 + 255) / 256;

    for (int i = 0; i < LL; i++) {
        float* z = zb[i & 1];
        float* t = bufT;

        cudaMemcpyAsync(z, hcur, sizeof(float) * (size_t)NN * DD, cudaMemcpyDeviceToDevice, 0);
        scatter_add_kernel<<<scat_blocks, 256>>>(ei, hcur, z);

        cudaMemsetAsync(stats, 0, 4 * DD * sizeof(float), 0);

        gemm_bias_stats<<<gemm_grid, 256>>>(z, W1 + (size_t)i * DD * DD, b1 + i * DD,
                                            t, stats, stats + DD, NN);
        bn_prep_kernel<<<1, 320>>>(stats, stats + DD, g1 + i * DD, be1 + i * DD,
                                   stats + 4 * DD, stats + 5 * DD);
        bn_relu_kernel<<<bn_blocks, 256>>>(t, stats + 4 * DD, stats + 5 * DD);

        gemm_bias_stats<<<gemm_grid, 256>>>(t, W2 + (size_t)i * DD * DD, b2 + i * DD,
                                            z, stats + 2 * DD, stats + 3 * DD, NN);
        bn_prep_kernel<<<1, 320>>>(stats + 2 * DD, stats + 3 * DD, bng + i * DD, bnb + i * DD,
                                   stats + 6 * DD, stats + 7 * DD);
        bn_relu_kernel<<<bn_blocks, 256>>>(z, stats + 6 * DD, stats + 7 * DD);

        pool_kernel<<<pg, 128>>>(z, batch, pooled + (size_t)(i + 1) * NGR * DD, nullptr);
        hcur = z;
    }

    head_kernel<<<NGR, CC>>>(pooled, counts, fcW, fcb, out);
}

// round 5
// speedup vs baseline: 1.4005x; 1.4005x over previous
#include <cuda_runtime.h>
#include <cuda_bf16.h>
#include <cstdint>

#define NN 50000
#define DD 300
#define KP 320          // K padded to 10*32
#define NP 320          // N padded to 5*64
#define EE 400000
#define LL 5
#define CC 128
#define NGR 256
#define BN_EPS 1e-5f

typedef unsigned long long u64;

// ---------------- device scratch ----------------
__device__ float g_bufA[NN * DD];
__device__ float g_bufB[NN * DD];
__device__ float g_bufT[NN * DD];
__device__ __nv_bfloat16 g_h0[NN * KP];        // hi split of current GEMM input
__device__ __nv_bfloat16 g_h1[NN * KP];        // lo split
__device__ __nv_bfloat16 g_wth[10 * NP * KP];  // transposed weight hi: [w][n][k]
__device__ __nv_bfloat16 g_wtl[10 * NP * KP];  // transposed weight lo
__device__ float g_pooled[(LL + 1) * NGR * DD];
__device__ float g_counts[NGR];
__device__ float g_stats[8 * DD];

// ---------------- PTX helpers (all arch-agnostic: sm_80+) ----------------
__device__ __forceinline__ uint32_t smem_u32(const void* p) {
    uint32_t a;
    asm("{ .reg .u64 t; cvta.to.shared.u64 t, %1; cvt.u32.u64 %0, t; }" : "=r"(a) : "l"(p));
    return a;
}
__device__ __forceinline__ void cpasync16(uint32_t dst, const void* src, int srcsize) {
    asm volatile("cp.async.cg.shared.global [%0], [%1], 16, %2;"
                 :: "r"(dst), "l"(src), "r"(srcsize) : "memory");
}
__device__ __forceinline__ void cp_commit() {
    asm volatile("cp.async.commit_group;" ::: "memory");
}
template<int N> __device__ __forceinline__ void cp_wait() {
    asm volatile("cp.async.wait_group %0;" :: "n"(N) : "memory");
}
__device__ __forceinline__ void ldsm4(uint32_t& r0, uint32_t& r1, uint32_t& r2, uint32_t& r3,
                                      uint32_t addr) {
    asm volatile("ldmatrix.sync.aligned.m8n8.x4.shared.b16 {%0,%1,%2,%3}, [%4];"
                 : "=r"(r0), "=r"(r1), "=r"(r2), "=r"(r3) : "r"(addr));
}
__device__ __forceinline__ void mma_bf16(float* c, const uint32_t* a, const uint32_t* b) {
    asm volatile("mma.sync.aligned.m16n8k16.row.col.f32.bf16.bf16.f32 "
                 "{%0,%1,%2,%3}, {%4,%5,%6,%7}, {%8,%9}, {%0,%1,%2,%3};"
                 : "+f"(c[0]), "+f"(c[1]), "+f"(c[2]), "+f"(c[3])
                 : "r"(a[0]), "r"(a[1]), "r"(a[2]), "r"(a[3]), "r"(b[0]), "r"(b[1]));
}

// smem tile addressing: rows of 64B (32 bf16), 4x16B units, XOR swizzle on (row>>1)&3
__device__ __forceinline__ uint32_t tile_off(int row, int c) {
    return (uint32_t)(row * 64 + ((c ^ ((row >> 1) & 3)) << 4));
}

// ---------------- weight transpose + bf16 hi/lo split ----------------
__global__ void wsplit_kernel(const float* __restrict__ W1, const float* __restrict__ W2,
                              __nv_bfloat16* __restrict__ wth, __nv_bfloat16* __restrict__ wtl)
{
    int idx = blockIdx.x * blockDim.x + threadIdx.x;
    if (idx >= 10 * NP * KP) return;
    int w = idx / (NP * KP);
    int r = idx - w * NP * KP;
    int n = r / KP, k = r - n * KP;
    float v = 0.f;
    if (n < DD && k < DD)
        v = (w < 5) ? W1[(size_t)w * DD * DD + (size_t)k * DD + n]
                    : W2[(size_t)(w - 5) * DD * DD + (size_t)k * DD + n];
    __nv_bfloat16 h = __float2bfloat16(v);
    __nv_bfloat16 l = __float2bfloat16(v - __bfloat162float(h));
    wth[idx] = h; wtl[idx] = l;
}

// ---------------- fp32 -> bf16 hi/lo split (padded K) ----------------
__global__ void split_kernel(const float* __restrict__ z,
                             __nv_bfloat16* __restrict__ h0, __nv_bfloat16* __restrict__ h1)
{
    int idx = blockIdx.x * blockDim.x + threadIdx.x;
    if (idx >= NN * 80) return;
    int row = idx / 80, c4 = idx - row * 80;
    int c = c4 * 4;
    float4 v = make_float4(0.f, 0.f, 0.f, 0.f);
    if (c + 3 < DD) v = *reinterpret_cast<const float4*>(z + (size_t)row * DD + c);
    ushort4 uh, ul;
    float f[4] = { v.x, v.y, v.z, v.w };
    unsigned short* ph = &uh.x; unsigned short* pl = &ul.x;
#pragma unroll
    for (int t = 0; t < 4; t++) {
        __nv_bfloat16 h = __float2bfloat16(f[t]);
        __nv_bfloat16 l = __float2bfloat16(f[t] - __bfloat162float(h));
        ph[t] = __bfloat16_as_ushort(h); pl[t] = __bfloat16_as_ushort(l);
    }
    *reinterpret_cast<ushort4*>(h0 + (size_t)row * KP + c) = uh;
    *reinterpret_cast<ushort4*>(h1 + (size_t)row * KP + c) = ul;
}

// ---------------- BN apply + ReLU -> bf16 hi/lo split ----------------
__global__ void bn_relu_split_kernel(const float* __restrict__ t,
                                     const float* __restrict__ scale, const float* __restrict__ shift,
                                     __nv_bfloat16* __restrict__ h0, __nv_bfloat16* __restrict__ h1)
{
    int idx = blockIdx.x * blockDim.x + threadIdx.x;
    if (idx >= NN * 80) return;
    int row = idx / 80, c4 = idx - row * 80;
    int c = c4 * 4;
    float f[4] = { 0.f, 0.f, 0.f, 0.f };
    if (c + 3 < DD) {
        float4 v = *reinterpret_cast<const float4*>(t + (size_t)row * DD + c);
        f[0] = fmaxf(v.x * scale[c] + shift[c], 0.f);
        f[1] = fmaxf(v.y * scale[c + 1] + shift[c + 1], 0.f);
        f[2] = fmaxf(v.z * scale[c + 2] + shift[c + 2], 0.f);
        f[3] = fmaxf(v.w * scale[c + 3] + shift[c + 3], 0.f);
    }
    ushort4 uh, ul;
    unsigned short* ph = &uh.x; unsigned short* pl = &ul.x;
#pragma unroll
    for (int tt = 0; tt < 4; tt++) {
        __nv_bfloat16 h = __float2bfloat16(f[tt]);
        __nv_bfloat16 l = __float2bfloat16(f[tt] - __bfloat162float(h));
        ph[tt] = __bfloat16_as_ushort(h); pl[tt] = __bfloat16_as_ushort(l);
    }
    *reinterpret_cast<ushort4*>(h0 + (size_t)row * KP + c) = uh;
    *reinterpret_cast<ushort4*>(h1 + (size_t)row * KP + c) = ul;
}

// ---------------- bf16x3 mma.sync GEMM: out[M,300] = A @ W + bias, fused BN stats ----
// A as hi/lo bf16 [M,KP]; W transposed hi/lo bf16 [NP,KP] (= col-major B).
// Block 128x64, 8 warps (4x2), warp 32x32. K chunk 32, double-buffered cp.async.
// smem per stage: Ah 8K | Al 8K | Bh 4K | Bl 4K = 24KB; 2 stages = 48KB.
#define ST_AH 0
#define ST_AL 8192
#define ST_BH 16384
#define ST_BL 20480
#define ST_SZ 24576

__global__ void __launch_bounds__(256)
gemm_tc(const __nv_bfloat16* __restrict__ ah, const __nv_bfloat16* __restrict__ al,
        const __nv_bfloat16* __restrict__ bh, const __nv_bfloat16* __restrict__ bl,
        const float* __restrict__ bias, float* __restrict__ out,
        float* __restrict__ gsum, float* __restrict__ gsq, int M)
{
    __shared__ __align__(16) char smem[2 * ST_SZ];
    const uint32_t sb = smem_u32(smem);
    const int tid = threadIdx.x;
    const int lane = tid & 31;
    const int w = tid >> 5;
    const int wm = w >> 1, wn = w & 1;
    const int n0 = blockIdx.x * 64;
    const int m0 = blockIdx.y * 128;

    float acc[2][4][4];
#pragma unroll
    for (int mt = 0; mt < 2; mt++)
#pragma unroll
        for (int nt = 0; nt < 4; nt++)
#pragma unroll
            for (int q = 0; q < 4; q++) acc[mt][nt][q] = 0.f;

    const int ar0 = (tid * 2) >> 2, ac0 = (tid * 2) & 3;
    const int ar1 = (tid * 2 + 1) >> 2, ac1 = (tid * 2 + 1) & 3;
    const int br = tid >> 2, bc = tid & 3;
    const uint32_t dA0 = tile_off(ar0, ac0), dA1 = tile_off(ar1, ac1), dB = tile_off(br, bc);
    const int szA0 = (m0 + ar0 < M) ? 16 : 0;
    const int szA1 = (m0 + ar1 < M) ? 16 : 0;

#define LOAD_STAGE(kc, s) do {                                                        \
        int k0_ = (kc) * 32;                                                          \
        uint32_t base_ = sb + (s) * ST_SZ;                                            \
        cpasync16(base_ + ST_AH + dA0, ah + (size_t)(m0 + ar0) * KP + k0_ + ac0 * 8, szA0); \
        cpasync16(base_ + ST_AH + dA1, ah + (size_t)(m0 + ar1) * KP + k0_ + ac1 * 8, szA1); \
        cpasync16(base_ + ST_AL + dA0, al + (size_t)(m0 + ar0) * KP + k0_ + ac0 * 8, szA0); \
        cpasync16(base_ + ST_AL + dA1, al + (size_t)(m0 + ar1) * KP + k0_ + ac1 * 8, szA1); \
        cpasync16(base_ + ST_BH + dB, bh + (size_t)(n0 + br) * KP + k0_ + bc * 8, 16);      \
        cpasync16(base_ + ST_BL + dB, bl + (size_t)(n0 + br) * KP + k0_ + bc * 8, 16);      \
        cp_commit();                                                                  \
    } while (0)

    LOAD_STAGE(0, 0);

    const int arow = wm * 32 + (lane & 7) + ((lane >> 3) & 1) * 8;   // + mt*16
    const int acu = lane >> 4;                                        // + 2*k16
    const int brow = wn * 32 + (lane & 7) + ((lane >> 4) & 1) * 8;   // + g*16
    const int bcu = (lane >> 3) & 1;                                  // + 2*k16

    for (int kc = 0; kc < 10; kc++) {
        if (kc < 9) LOAD_STAGE(kc + 1, (kc + 1) & 1);
        if (kc < 9) cp_wait<1>(); else cp_wait<0>();
        __syncthreads();

        const uint32_t base = sb + (kc & 1) * ST_SZ;
#pragma unroll
        for (int k16 = 0; k16 < 2; k16++) {
            uint32_t Ah[2][4], Al[2][4], Bh[2][4], Bl[2][4];
#pragma unroll
            for (int mt = 0; mt < 2; mt++) {
                uint32_t oa = tile_off(arow + mt * 16, acu + 2 * k16);
                ldsm4(Ah[mt][0], Ah[mt][1], Ah[mt][2], Ah[mt][3], base + ST_AH + oa);
                ldsm4(Al[mt][0], Al[mt][1], Al[mt][2], Al[mt][3], base + ST_AL + oa);
            }
#pragma unroll
            for (int g = 0; g < 2; g++) {
                uint32_t ob = tile_off(brow + g * 16, bcu + 2 * k16);
                ldsm4(Bh[g][0], Bh[g][1], Bh[g][2], Bh[g][3], base + ST_BH + ob);
                ldsm4(Bl[g][0], Bl[g][1], Bl[g][2], Bl[g][3], base + ST_BL + ob);
            }
#pragma unroll
            for (int mt = 0; mt < 2; mt++)
#pragma unroll
                for (int g = 0; g < 2; g++)
#pragma unroll
                    for (int sub = 0; sub < 2; sub++) {
                        int nt = g * 2 + sub;
                        mma_bf16(acc[mt][nt], Ah[mt], &Bh[g][sub * 2]);
                        mma_bf16(acc[mt][nt], Al[mt], &Bh[g][sub * 2]);
                        mma_bf16(acc[mt][nt], Ah[mt], &Bl[g][sub * 2]);
                    }
        }
        __syncthreads();
    }

    // ---- epilogue: bias + stats + store ----
    float* ssum = reinterpret_cast<float*>(smem);          // 64 floats
    float* ssq  = reinterpret_cast<float*>(smem + 256);    // 64 floats
    if (tid < 64) { ssum[tid] = 0.f; ssq[tid] = 0.f; }
    __syncthreads();

    float ls[8], lq[8];
#pragma unroll
    for (int j = 0; j < 8; j++) { ls[j] = 0.f; lq[j] = 0.f; }

#pragma unroll
    for (int nt = 0; nt < 4; nt++) {
        int cl0 = wn * 32 + nt * 8 + 2 * (lane & 3);
        int gc0 = n0 + cl0;
        float bb0 = (gc0 < DD) ? bias[gc0] : 0.f;
        float bb1 = (gc0 + 1 < DD) ? bias[gc0 + 1] : 0.f;
#pragma unroll
        for (int mt = 0; mt < 2; mt++) {
            int r0 = m0 + wm * 32 + mt * 16 + (lane >> 2);
            int r1 = r0 + 8;
            float v0 = acc[mt][nt][0] + bb0;
            float v1 = acc[mt][nt][1] + bb1;
            float v2 = acc[mt][nt][2] + bb0;
            float v3 = acc[mt][nt][3] + bb1;
            if (r0 < M && gc0 < DD)
                *reinterpret_cast<float2*>(out + (size_t)r0 * DD + gc0) = make_float2(v0, v1);
            if (r1 < M && gc0 < DD)
                *reinterpret_cast<float2*>(out + (size_t)r1 * DD + gc0) = make_float2(v2, v3);
            float s0 = (r0 < M) ? v0 : 0.f, s2 = (r1 < M) ? v2 : 0.f;
            float s1 = (r0 < M) ? v1 : 0.f, s3 = (r1 < M) ? v3 : 0.f;
            ls[nt * 2]     += s0 + s2;  lq[nt * 2]     += s0 * s0 + s2 * s2;
            ls[nt * 2 + 1] += s1 + s3;  lq[nt * 2 + 1] += s1 * s1 + s3 * s3;
        }
    }
#pragma unroll
    for (int nt = 0; nt < 4; nt++) {
        int cl0 = wn * 32 + nt * 8 + 2 * (lane & 3);
        atomicAdd(&ssum[cl0], ls[nt * 2]);     atomicAdd(&ssq[cl0], lq[nt * 2]);
        atomicAdd(&ssum[cl0 + 1], ls[nt * 2 + 1]); atomicAdd(&ssq[cl0 + 1], lq[nt * 2 + 1]);
    }
    __syncthreads();
    if (tid < 64) {
        int n = n0 + tid;
        if (n < DD) { atomicAdd(gsum + n, ssum[tid]); atomicAdd(gsq + n, ssq[tid]); }
    }
#undef LOAD_STAGE
}

// ---------------- scatter-add (int32 indices) ----------------
__global__ void scatter_add_kernel(const int* __restrict__ ei,
                                   const float* __restrict__ h, float* __restrict__ z)
{
    int w = blockIdx.x * blockDim.x + threadIdx.x;
    if (w >= EE * 75) return;
    int e = w / 75;
    int q = (w - e * 75) * 4;
    int s = ei[e];
    int d = ei[EE + e];
    float4 v = *reinterpret_cast<const float4*>(h + (size_t)s * DD + q);
    float* p = z + (size_t)d * DD + q;
    atomicAdd(p + 0, v.x);
    atomicAdd(p + 1, v.y);
    atomicAdd(p + 2, v.z);
    atomicAdd(p + 3, v.w);
}

// ---------------- BN prep ----------------
__global__ void bn_prep_kernel(const float* __restrict__ gsum, const float* __restrict__ gsq,
                               const float* __restrict__ gamma, const float* __restrict__ beta,
                               float* __restrict__ scale, float* __restrict__ shift)
{
    int c = blockIdx.x * blockDim.x + threadIdx.x;
    if (c >= DD) return;
    const float invN = 1.0f / (float)NN;
    float mu = gsum[c] * invN;
    float var = gsq[c] * invN - mu * mu;
    float rs = rsqrtf(var + BN_EPS);
    float sc = rs * gamma[c];
    scale[c] = sc;
    shift[c] = beta[c] - mu * sc;
}

// ---------------- BN apply + ReLU (fp32 in place) ----------------
__global__ void bn_relu_kernel(float* __restrict__ t,
                               const float* __restrict__ scale, const float* __restrict__ shift)
{
    int idx = blockIdx.x * blockDim.x + threadIdx.x;
    if (idx >= NN * 75) return;
    int c = (idx % 75) * 4;
    float4 v = *reinterpret_cast<float4*>(t + (size_t)idx * 4);
    float4 r;
    r.x = fmaxf(v.x * scale[c + 0] + shift[c + 0], 0.f);
    r.y = fmaxf(v.y * scale[c + 1] + shift[c + 1], 0.f);
    r.z = fmaxf(v.z * scale[c + 2] + shift[c + 2], 0.f);
    r.w = fmaxf(v.w * scale[c + 3] + shift[c + 3], 0.f);
    *reinterpret_cast<float4*>(t + (size_t)idx * 4) = r;
}

// ---------------- per-graph pooling (sorted batch) ----------------
__global__ void pool_kernel(const float* __restrict__ h, const int* __restrict__ batch,
                            float* __restrict__ pooled, float* __restrict__ counts)
{
    int g = blockIdx.x;
    int lo = 0, hi = NN;
    while (lo < hi) { int mid = (lo + hi) >> 1; if (batch[mid] < g) lo = mid + 1; else hi = mid; }
    int s = lo;
    lo = s; hi = NN;
    while (lo < hi) { int mid = (lo + hi) >> 1; if (batch[mid] < g + 1) lo = mid + 1; else hi = mid; }
    int e = lo;
    if (counts && threadIdx.x == 0 && blockIdx.y == 0) counts[g] = (float)(e - s);
    int c = blockIdx.y * 100 + threadIdx.x;
    if (threadIdx.x < 100) {
        float acc = 0.f;
        for (int n = s; n < e; n++) acc += h[(size_t)n * DD + c];
        pooled[(size_t)g * DD + c] = acc;
    }
}

// ---------------- readout heads ----------------
__global__ void head_kernel(const float* __restrict__ pooled, const float* __restrict__ counts,
                            const float* __restrict__ fcW, const float* __restrict__ fcb,
                            float* __restrict__ out)
{
    int g = blockIdx.x;
    int c = threadIdx.x;
    float inv = 1.0f / fmaxf(counts[g], 1.0f);
    float acc = 0.f;
#pragma unroll
    for (int i = 0; i <= LL; i++) {
        const float* p = pooled + ((size_t)i * NGR + g) * DD;
        const float* Wp = fcW + (size_t)i * DD * CC + c;
        float s = 0.f;
#pragma unroll 4
        for (int k = 0; k < DD; k++) s += __ldg(&p[k]) * __ldg(&Wp[(size_t)k * CC]);
        acc += s * inv + __ldg(&fcb[i * CC + c]);
    }
    out[(size_t)g * CC + c] = acc;
}

// ---------------- launch ----------------
extern "C" void kernel_launch(void* const* d_in, const int* in_sizes, int n_in,
                              void* d_out, int out_size)
{
    int ix, iei, ibatch, iW1, ib1, ig1, ibe1, iW2, ib2, ibng, ibnb, ifcW, ifcb;
    if (in_sizes[0] == NN) {  // alphabetical
        ibatch = 0; ibnb = 1; ibng = 2; iei = 3; ifcW = 4; ifcb = 5;
        iW1 = 6; iW2 = 7; ib1 = 8; ib2 = 9; ibe1 = 10; ig1 = 11; ix = 12;
    } else {                  // insertion order
        ix = 0; iei = 1; ibatch = 2; iW1 = 3; ib1 = 4; ig1 = 5; ibe1 = 6;
        iW2 = 7; ib2 = 8; ibng = 9; ibnb = 10; ifcW = 11; ifcb = 12;
    }
    const float* x     = (const float*)d_in[ix];
    const int*   ei    = (const int*)d_in[iei];
    const int*   batch = (const int*)d_in[ibatch];
    const float* W1    = (const float*)d_in[iW1];
    const float* b1    = (const float*)d_in[ib1];
    const float* g1    = (const float*)d_in[ig1];
    const float* be1   = (const float*)d_in[ibe1];
    const float* W2    = (const float*)d_in[iW2];
    const float* b2    = (const float*)d_in[ib2];
    const float* bng   = (const float*)d_in[ibng];
    const float* bnb   = (const float*)d_in[ibnb];
    const float* fcW   = (const float*)d_in[ifcW];
    const float* fcb   = (const float*)d_in[ifcb];
    float* out = (float*)d_out;

    float *bufA, *bufB, *bufT, *pooled, *counts, *stats;
    __nv_bfloat16 *h0, *h1, *wth, *wtl;
    cudaGetSymbolAddress((void**)&bufA,   g_bufA);
    cudaGetSymbolAddress((void**)&bufB,   g_bufB);
    cudaGetSymbolAddress((void**)&bufT,   g_bufT);
    cudaGetSymbolAddress((void**)&pooled, g_pooled);
    cudaGetSymbolAddress((void**)&counts, g_counts);
    cudaGetSymbolAddress((void**)&stats,  g_stats);
    cudaGetSymbolAddress((void**)&h0,     g_h0);
    cudaGetSymbolAddress((void**)&h1,     g_h1);
    cudaGetSymbolAddress((void**)&wth,    g_wth);
    cudaGetSymbolAddress((void**)&wtl,    g_wtl);

    // weights: transpose + bf16 split (tiny, once per launch)
    wsplit_kernel<<<(10 * NP * KP + 255) / 256, 256>>>(W1, W2, wth, wtl);

    dim3 pg(NGR, 3);
    pool_kernel<<<pg, 128>>>(x, batch, pooled, counts);

    const float* hcur = x;
    float* zb[2] = { bufA, bufB };
    const dim3 gemm_grid(NP / 64, (NN + 127) / 128);   // (5, 391)
    const int scat_blocks = (EE * 75 + 255) / 256;
    const int split_blocks = (NN * 80 + 255) / 256;
    const int bn_blocks = (NN * 75 + 255) / 256;

    for (int i = 0; i < LL; i++) {
        float* z = zb[i & 1];

        cudaMemcpyAsync(z, hcur, sizeof(float) * (size_t)NN * DD, cudaMemcpyDeviceToDevice, 0);
        scatter_add_kernel<<<scat_blocks, 256>>>(ei, hcur, z);
        split_kernel<<<split_blocks, 256>>>(z, h0, h1);

        cudaMemsetAsync(stats, 0, 4 * DD * sizeof(float), 0);

        gemm_tc<<<gemm_grid, 256>>>(h0, h1,
                                    wth + (size_t)i * NP * KP, wtl + (size_t)i * NP * KP,
                                    b1 + i * DD, bufT, stats, stats + DD, NN);
        bn_prep_kernel<<<1, 320>>>(stats, stats + DD, g1 + i * DD, be1 + i * DD,
                                   stats + 4 * DD, stats + 5 * DD);
        bn_relu_split_kernel<<<split_blocks, 256>>>(bufT, stats + 4 * DD, stats + 5 * DD, h0, h1);

        gemm_tc<<<gemm_grid, 256>>>(h0, h1,
                                    wth + (size_t)(i + 5) * NP * KP, wtl + (size_t)(i + 5) * NP * KP,
                                    b2 + i * DD, z, stats + 2 * DD, stats + 3 * DD, NN);
        bn_prep_kernel<<<1, 320>>>(stats + 2 * DD, stats + 3 * DD, bng + i * DD, bnb + i * DD,
                                   stats + 6 * DD, stats + 7 * DD);
        bn_relu_kernel<<<bn_blocks, 256>>>(z, stats + 6 * DD, stats + 7 * DD);

        pool_kernel<<<pg, 128>>>(z, batch, pooled + (size_t)(i + 1) * NGR * DD, nullptr);
        hcur = z;
    }

    head_kernel<<<NGR, CC>>>(pooled, counts, fcW, fcb, out);
}

// round 6
// speedup vs baseline: 2.0581x; 1.4695x over previous
#include <cuda_runtime.h>
#include <cuda_bf16.h>
#include <cstdint>

#define NN 50000
#define DD 300
#define KP 320          // K padded to 10*32
#define NP 320          // N padded to 5*64
#define EE 400000
#define LL 5
#define CC 128
#define NGR 256
#define BN_EPS 1e-5f

typedef unsigned long long u64;

// ---------------- device scratch ----------------
__device__ float g_bufA[NN * DD];
__device__ float g_bufB[NN * DD];
__device__ float g_bufT[NN * DD];
__device__ __nv_bfloat16 g_h0[NN * KP];        // hi split of current GEMM input
__device__ __nv_bfloat16 g_h1[NN * KP];        // lo split
__device__ __nv_bfloat16 g_wth[10 * NP * KP];  // transposed weight hi: [w][n][k]
__device__ __nv_bfloat16 g_wtl[10 * NP * KP];  // transposed weight lo
__device__ float g_pooled[(LL + 1) * NGR * DD];
__device__ float g_counts[NGR];
__device__ float g_stats[8 * DD];
__device__ float g_ident[2 * DD];              // [0..DD)=1, [DD..2DD)=0
__device__ int g_rowptr[NN + 1];
__device__ int g_cur[NN];
__device__ int g_eidx[EE];

// ---------------- PTX helpers (all arch-agnostic: sm_80+) ----------------
__device__ __forceinline__ uint32_t smem_u32(const void* p) {
    uint32_t a;
    asm("{ .reg .u64 t; cvta.to.shared.u64 t, %1; cvt.u32.u64 %0, t; }" : "=r"(a) : "l"(p));
    return a;
}
__device__ __forceinline__ void cpasync16(uint32_t dst, const void* src, int srcsize) {
    asm volatile("cp.async.cg.shared.global [%0], [%1], 16, %2;"
                 :: "r"(dst), "l"(src), "r"(srcsize) : "memory");
}
__device__ __forceinline__ void cp_commit() {
    asm volatile("cp.async.commit_group;" ::: "memory");
}
template<int N> __device__ __forceinline__ void cp_wait() {
    asm volatile("cp.async.wait_group %0;" :: "n"(N) : "memory");
}
__device__ __forceinline__ void ldsm4(uint32_t& r0, uint32_t& r1, uint32_t& r2, uint32_t& r3,
                                      uint32_t addr) {
    asm volatile("ldmatrix.sync.aligned.m8n8.x4.shared.b16 {%0,%1,%2,%3}, [%4];"
                 : "=r"(r0), "=r"(r1), "=r"(r2), "=r"(r3) : "r"(addr));
}
__device__ __forceinline__ void mma_bf16(float* c, const uint32_t* a, const uint32_t* b) {
    asm volatile("mma.sync.aligned.m16n8k16.row.col.f32.bf16.bf16.f32 "
                 "{%0,%1,%2,%3}, {%4,%5,%6,%7}, {%8,%9}, {%0,%1,%2,%3};"
                 : "+f"(c[0]), "+f"(c[1]), "+f"(c[2]), "+f"(c[3])
                 : "r"(a[0]), "r"(a[1]), "r"(a[2]), "r"(a[3]), "r"(b[0]), "r"(b[1]));
}
__device__ __forceinline__ uint32_t tile_off(int row, int c) {
    return (uint32_t)(row * 64 + ((c ^ ((row >> 1) & 3)) << 4));
}

// ---------------- CSR build ----------------
__global__ void hist_kernel(const int* __restrict__ ei, int* __restrict__ deg) {
    int e = blockIdx.x * blockDim.x + threadIdx.x;
    if (e < EE) atomicAdd(&deg[ei[EE + e]], 1);
}

__global__ void scan_kernel(int* __restrict__ deg_cur, int* __restrict__ rowptr) {
    __shared__ int sm[1024];
    __shared__ int carry;
    int t = threadIdx.x;
    if (t == 0) { carry = 0; rowptr[0] = 0; }
    __syncthreads();
    for (int base = 0; base < NN; base += 1024) {
        int i = base + t;
        int v = (i < NN) ? deg_cur[i] : 0;
        sm[t] = v;
        __syncthreads();
        for (int off = 1; off < 1024; off <<= 1) {
            int u = (t >= off) ? sm[t - off] : 0;
            __syncthreads();
            sm[t] += u;
            __syncthreads();
        }
        int inc = sm[t];
        int c = carry;
        if (i < NN) { rowptr[i + 1] = c + inc; deg_cur[i] = c + inc - v; }
        __syncthreads();
        if (t == 0) carry = c + sm[1023];
        __syncthreads();
    }
}

__global__ void fill_kernel(const int* __restrict__ ei, int* __restrict__ cur,
                            int* __restrict__ eidx) {
    int e = blockIdx.x * blockDim.x + threadIdx.x;
    if (e >= EE) return;
    int pos = atomicAdd(&cur[ei[EE + e]], 1);
    eidx[pos] = ei[e];
}

__global__ void init_ident_kernel(float* __restrict__ ident) {
    int c = blockIdx.x * blockDim.x + threadIdx.x;
    if (c < DD) { ident[c] = 1.f; ident[DD + c] = 0.f; }
}

// ---------------- weight transpose + bf16 hi/lo split ----------------
__global__ void wsplit_kernel(const float* __restrict__ W1, const float* __restrict__ W2,
                              __nv_bfloat16* __restrict__ wth, __nv_bfloat16* __restrict__ wtl)
{
    int idx = blockIdx.x * blockDim.x + threadIdx.x;
    if (idx >= 10 * NP * KP) return;
    int w = idx / (NP * KP);
    int r = idx - w * NP * KP;
    int n = r / KP, k = r - n * KP;
    float v = 0.f;
    if (n < DD && k < DD)
        v = (w < 5) ? W1[(size_t)w * DD * DD + (size_t)k * DD + n]
                    : W2[(size_t)(w - 5) * DD * DD + (size_t)k * DD + n];
    __nv_bfloat16 h = __float2bfloat16(v);
    __nv_bfloat16 l = __float2bfloat16(v - __bfloat162float(h));
    wth[idx] = h; wtl[idx] = l;
}

// ---------------- fused: BN/ReLU(on the fly) + GIN aggregate + bf16 split ----------------
// h = pre-activation fp32 [NN,DD]; f(v) = (relu?) (v*scale + shift).
// Per warp: one node. z = f(h[n]) + sum_e f(h[src_e]); write bf16 hi/lo [NN,KP].
__global__ void __launch_bounds__(256)
agg_split_kernel(const float* __restrict__ h,
                 const float* __restrict__ scale, const float* __restrict__ shift, int do_relu,
                 const int* __restrict__ rowptr, const int* __restrict__ eidx,
                 __nv_bfloat16* __restrict__ h0, __nv_bfloat16* __restrict__ h1)
{
    int n = (blockIdx.x * 256 + threadIdx.x) >> 5;
    int lane = threadIdx.x & 31;
    if (n >= NN) return;
    int r0 = __ldg(&rowptr[n]), r1 = __ldg(&rowptr[n + 1]);
#pragma unroll
    for (int cb = 0; cb < KP; cb += 64) {
        int c0 = cb + lane, c1 = cb + 32 + lane;
        bool v0 = c0 < DD, v1 = c1 < DD;
        float s0 = v0 ? __ldg(&scale[c0]) : 0.f, t0 = v0 ? __ldg(&shift[c0]) : 0.f;
        float s1 = v1 ? __ldg(&scale[c1]) : 0.f, t1 = v1 ? __ldg(&shift[c1]) : 0.f;
        float a0 = 0.f, a1 = 0.f;
        if (v0) { float v = h[(size_t)n * DD + c0] * s0 + t0; a0 = do_relu ? fmaxf(v, 0.f) : v; }
        if (v1) { float v = h[(size_t)n * DD + c1] * s1 + t1; a1 = do_relu ? fmaxf(v, 0.f) : v; }
        for (int e = r0; e < r1; e++) {
            int s = __ldg(&eidx[e]);
            if (v0) { float v = __ldg(&h[(size_t)s * DD + c0]) * s0 + t0; a0 += do_relu ? fmaxf(v, 0.f) : v; }
            if (v1) { float v = __ldg(&h[(size_t)s * DD + c1]) * s1 + t1; a1 += do_relu ? fmaxf(v, 0.f) : v; }
        }
        __nv_bfloat16 hh0 = __float2bfloat16(a0);
        __nv_bfloat16 ll0 = __float2bfloat16(a0 - __bfloat162float(hh0));
        __nv_bfloat16 hh1 = __float2bfloat16(a1);
        __nv_bfloat16 ll1 = __float2bfloat16(a1 - __bfloat162float(hh1));
        h0[(size_t)n * KP + c0] = hh0; h1[(size_t)n * KP + c0] = ll0;
        h0[(size_t)n * KP + c1] = hh1; h1[(size_t)n * KP + c1] = ll1;
    }
}

// ---------------- BN apply + ReLU -> bf16 hi/lo split (mid-layer) ----------------
__global__ void bn_relu_split_kernel(const float* __restrict__ t,
                                     const float* __restrict__ scale, const float* __restrict__ shift,
                                     __nv_bfloat16* __restrict__ h0, __nv_bfloat16* __restrict__ h1)
{
    int idx = blockIdx.x * blockDim.x + threadIdx.x;
    if (idx >= NN * 80) return;
    int row = idx / 80, c4 = idx - row * 80;
    int c = c4 * 4;
    float f[4] = { 0.f, 0.f, 0.f, 0.f };
    if (c + 3 < DD) {
        float4 v = *reinterpret_cast<const float4*>(t + (size_t)row * DD + c);
        f[0] = fmaxf(v.x * scale[c] + shift[c], 0.f);
        f[1] = fmaxf(v.y * scale[c + 1] + shift[c + 1], 0.f);
        f[2] = fmaxf(v.z * scale[c + 2] + shift[c + 2], 0.f);
        f[3] = fmaxf(v.w * scale[c + 3] + shift[c + 3], 0.f);
    }
    ushort4 uh, ul;
    unsigned short* ph = &uh.x; unsigned short* pl = &ul.x;
#pragma unroll
    for (int tt = 0; tt < 4; tt++) {
        __nv_bfloat16 h = __float2bfloat16(f[tt]);
        __nv_bfloat16 l = __float2bfloat16(f[tt] - __bfloat162float(h));
        ph[tt] = __bfloat16_as_ushort(h); pl[tt] = __bfloat16_as_ushort(l);
    }
    *reinterpret_cast<ushort4*>(h0 + (size_t)row * KP + c) = uh;
    *reinterpret_cast<ushort4*>(h1 + (size_t)row * KP + c) = ul;
}

// ---------------- bf16x3 mma.sync GEMM (same as R5) ----------------
#define ST_AH 0
#define ST_AL 8192
#define ST_BH 16384
#define ST_BL 20480
#define ST_SZ 24576

__global__ void __launch_bounds__(256)
gemm_tc(const __nv_bfloat16* __restrict__ ah, const __nv_bfloat16* __restrict__ al,
        const __nv_bfloat16* __restrict__ bh, const __nv_bfloat16* __restrict__ bl,
        const float* __restrict__ bias, float* __restrict__ out,
        float* __restrict__ gsum, float* __restrict__ gsq, int M)
{
    __shared__ __align__(16) char smem[2 * ST_SZ];
    const uint32_t sb = smem_u32(smem);
    const int tid = threadIdx.x;
    const int lane = tid & 31;
    const int w = tid >> 5;
    const int wm = w >> 1, wn = w & 1;
    const int n0 = blockIdx.x * 64;
    const int m0 = blockIdx.y * 128;

    float acc[2][4][4];
#pragma unroll
    for (int mt = 0; mt < 2; mt++)
#pragma unroll
        for (int nt = 0; nt < 4; nt++)
#pragma unroll
            for (int q = 0; q < 4; q++) acc[mt][nt][q] = 0.f;

    const int ar0 = (tid * 2) >> 2, ac0 = (tid * 2) & 3;
    const int ar1 = (tid * 2 + 1) >> 2, ac1 = (tid * 2 + 1) & 3;
    const int br = tid >> 2, bc = tid & 3;
    const uint32_t dA0 = tile_off(ar0, ac0), dA1 = tile_off(ar1, ac1), dB = tile_off(br, bc);
    const int szA0 = (m0 + ar0 < M) ? 16 : 0;
    const int szA1 = (m0 + ar1 < M) ? 16 : 0;

#define LOAD_STAGE(kc, s) do {                                                        \
        int k0_ = (kc) * 32;                                                          \
        uint32_t base_ = sb + (s) * ST_SZ;                                            \
        cpasync16(base_ + ST_AH + dA0, ah + (size_t)(m0 + ar0) * KP + k0_ + ac0 * 8, szA0); \
        cpasync16(base_ + ST_AH + dA1, ah + (size_t)(m0 + ar1) * KP + k0_ + ac1 * 8, szA1); \
        cpasync16(base_ + ST_AL + dA0, al + (size_t)(m0 + ar0) * KP + k0_ + ac0 * 8, szA0); \
        cpasync16(base_ + ST_AL + dA1, al + (size_t)(m0 + ar1) * KP + k0_ + ac1 * 8, szA1); \
        cpasync16(base_ + ST_BH + dB, bh + (size_t)(n0 + br) * KP + k0_ + bc * 8, 16);      \
        cpasync16(base_ + ST_BL + dB, bl + (size_t)(n0 + br) * KP + k0_ + bc * 8, 16);      \
        cp_commit();                                                                  \
    } while (0)

    LOAD_STAGE(0, 0);

    const int arow = wm * 32 + (lane & 7) + ((lane >> 3) & 1) * 8;
    const int acu = lane >> 4;
    const int brow = wn * 32 + (lane & 7) + ((lane >> 4) & 1) * 8;
    const int bcu = (lane >> 3) & 1;

    for (int kc = 0; kc < 10; kc++) {
        if (kc < 9) LOAD_STAGE(kc + 1, (kc + 1) & 1);
        if (kc < 9) cp_wait<1>(); else cp_wait<0>();
        __syncthreads();

        const uint32_t base = sb + (kc & 1) * ST_SZ;
#pragma unroll
        for (int k16 = 0; k16 < 2; k16++) {
            uint32_t Ah[2][4], Al[2][4], Bh[2][4], Bl[2][4];
#pragma unroll
            for (int mt = 0; mt < 2; mt++) {
                uint32_t oa = tile_off(arow + mt * 16, acu + 2 * k16);
                ldsm4(Ah[mt][0], Ah[mt][1], Ah[mt][2], Ah[mt][3], base + ST_AH + oa);
                ldsm4(Al[mt][0], Al[mt][1], Al[mt][2], Al[mt][3], base + ST_AL + oa);
            }
#pragma unroll
            for (int g = 0; g < 2; g++) {
                uint32_t ob = tile_off(brow + g * 16, bcu + 2 * k16);
                ldsm4(Bh[g][0], Bh[g][1], Bh[g][2], Bh[g][3], base + ST_BH + ob);
                ldsm4(Bl[g][0], Bl[g][1], Bl[g][2], Bl[g][3], base + ST_BL + ob);
            }
#pragma unroll
            for (int mt = 0; mt < 2; mt++)
#pragma unroll
                for (int g = 0; g < 2; g++)
#pragma unroll
                    for (int sub = 0; sub < 2; sub++) {
                        int nt = g * 2 + sub;
                        mma_bf16(acc[mt][nt], Ah[mt], &Bh[g][sub * 2]);
                        mma_bf16(acc[mt][nt], Al[mt], &Bh[g][sub * 2]);
                        mma_bf16(acc[mt][nt], Ah[mt], &Bl[g][sub * 2]);
                    }
        }
        __syncthreads();
    }

    float* ssum = reinterpret_cast<float*>(smem);
    float* ssq  = reinterpret_cast<float*>(smem + 256);
    if (tid < 64) { ssum[tid] = 0.f; ssq[tid] = 0.f; }
    __syncthreads();

    float ls[8], lq[8];
#pragma unroll
    for (int j = 0; j < 8; j++) { ls[j] = 0.f; lq[j] = 0.f; }

#pragma unroll
    for (int nt = 0; nt < 4; nt++) {
        int cl0 = wn * 32 + nt * 8 + 2 * (lane & 3);
        int gc0 = n0 + cl0;
        float bb0 = (gc0 < DD) ? bias[gc0] : 0.f;
        float bb1 = (gc0 + 1 < DD) ? bias[gc0 + 1] : 0.f;
#pragma unroll
        for (int mt = 0; mt < 2; mt++) {
            int r0 = m0 + wm * 32 + mt * 16 + (lane >> 2);
            int r1 = r0 + 8;
            float v0 = acc[mt][nt][0] + bb0;
            float v1 = acc[mt][nt][1] + bb1;
            float v2 = acc[mt][nt][2] + bb0;
            float v3 = acc[mt][nt][3] + bb1;
            if (r0 < M && gc0 < DD)
                *reinterpret_cast<float2*>(out + (size_t)r0 * DD + gc0) = make_float2(v0, v1);
            if (r1 < M && gc0 < DD)
                *reinterpret_cast<float2*>(out + (size_t)r1 * DD + gc0) = make_float2(v2, v3);
            float s0 = (r0 < M) ? v0 : 0.f, s2 = (r1 < M) ? v2 : 0.f;
            float s1 = (r0 < M) ? v1 : 0.f, s3 = (r1 < M) ? v3 : 0.f;
            ls[nt * 2]     += s0 + s2;  lq[nt * 2]     += s0 * s0 + s2 * s2;
            ls[nt * 2 + 1] += s1 + s3;  lq[nt * 2 + 1] += s1 * s1 + s3 * s3;
        }
    }
#pragma unroll
    for (int nt = 0; nt < 4; nt++) {
        int cl0 = wn * 32 + nt * 8 + 2 * (lane & 3);
        atomicAdd(&ssum[cl0], ls[nt * 2]);     atomicAdd(&ssq[cl0], lq[nt * 2]);
        atomicAdd(&ssum[cl0 + 1], ls[nt * 2 + 1]); atomicAdd(&ssq[cl0 + 1], lq[nt * 2 + 1]);
    }
    __syncthreads();
    if (tid < 64) {
        int n = n0 + tid;
        if (n < DD) { atomicAdd(gsum + n, ssum[tid]); atomicAdd(gsq + n, ssq[tid]); }
    }
#undef LOAD_STAGE
}

// ---------------- BN prep ----------------
__global__ void bn_prep_kernel(const float* __restrict__ gsum, const float* __restrict__ gsq,
                               const float* __restrict__ gamma, const float* __restrict__ beta,
                               float* __restrict__ scale, float* __restrict__ shift)
{
    int c = blockIdx.x * blockDim.x + threadIdx.x;
    if (c >= DD) return;
    const float invN = 1.0f / (float)NN;
    float mu = gsum[c] * invN;
    float var = gsq[c] * invN - mu * mu;
    float rs = rsqrtf(var + BN_EPS);
    float sc = rs * gamma[c];
    scale[c] = sc;
    shift[c] = beta[c] - mu * sc;
}

// ---------------- per-graph pooling with fused BN/ReLU ----------------
__global__ void pool_kernel(const float* __restrict__ h,
                            const float* __restrict__ scale, const float* __restrict__ shift,
                            int do_relu, const int* __restrict__ batch,
                            float* __restrict__ pooled, float* __restrict__ counts)
{
    int g = blockIdx.x;
    int lo = 0, hi = NN;
    while (lo < hi) { int mid = (lo + hi) >> 1; if (batch[mid] < g) lo = mid + 1; else hi = mid; }
    int s = lo;
    lo = s; hi = NN;
    while (lo < hi) { int mid = (lo + hi) >> 1; if (batch[mid] < g + 1) lo = mid + 1; else hi = mid; }
    int e = lo;
    if (counts && threadIdx.x == 0 && blockIdx.y == 0) counts[g] = (float)(e - s);
    int c = blockIdx.y * 100 + threadIdx.x;
    if (threadIdx.x < 100) {
        float sc = scale[c], sh = shift[c];
        float acc = 0.f;
        for (int n = s; n < e; n++) {
            float v = h[(size_t)n * DD + c] * sc + sh;
            if (do_relu) v = fmaxf(v, 0.f);
            acc += v;
        }
        pooled[(size_t)g * DD + c] = acc;
    }
}

// ---------------- readout heads ----------------
__global__ void head_kernel(const float* __restrict__ pooled, const float* __restrict__ counts,
                            const float* __restrict__ fcW, const float* __restrict__ fcb,
                            float* __restrict__ out)
{
    int g = blockIdx.x;
    int c = threadIdx.x;
    float inv = 1.0f / fmaxf(counts[g], 1.0f);
    float acc = 0.f;
#pragma unroll
    for (int i = 0; i <= LL; i++) {
        const float* p = pooled + ((size_t)i * NGR + g) * DD;
        const float* Wp = fcW + (size_t)i * DD * CC + c;
        float s = 0.f;
#pragma unroll 4
        for (int k = 0; k < DD; k++) s += __ldg(&p[k]) * __ldg(&Wp[(size_t)k * CC]);
        acc += s * inv + __ldg(&fcb[i * CC + c]);
    }
    out[(size_t)g * CC + c] = acc;
}

// ---------------- launch ----------------
extern "C" void kernel_launch(void* const* d_in, const int* in_sizes, int n_in,
                              void* d_out, int out_size)
{
    int ix, iei, ibatch, iW1, ib1, ig1, ibe1, iW2, ib2, ibng, ibnb, ifcW, ifcb;
    if (in_sizes[0] == NN) {  // alphabetical
        ibatch = 0; ibnb = 1; ibng = 2; iei = 3; ifcW = 4; ifcb = 5;
        iW1 = 6; iW2 = 7; ib1 = 8; ib2 = 9; ibe1 = 10; ig1 = 11; ix = 12;
    } else {                  // insertion order
        ix = 0; iei = 1; ibatch = 2; iW1 = 3; ib1 = 4; ig1 = 5; ibe1 = 6;
        iW2 = 7; ib2 = 8; ibng = 9; ibnb = 10; ifcW = 11; ifcb = 12;
    }
    const float* x     = (const float*)d_in[ix];
    const int*   ei    = (const int*)d_in[iei];
    const int*   batch = (const int*)d_in[ibatch];
    const float* W1    = (const float*)d_in[iW1];
    const float* b1    = (const float*)d_in[ib1];
    const float* g1    = (const float*)d_in[ig1];
    const float* be1   = (const float*)d_in[ibe1];
    const float* W2    = (const float*)d_in[iW2];
    const float* b2    = (const float*)d_in[ib2];
    const float* bng   = (const float*)d_in[ibng];
    const float* bnb   = (const float*)d_in[ibnb];
    const float* fcW   = (const float*)d_in[ifcW];
    const float* fcb   = (const float*)d_in[ifcb];
    float* out = (float*)d_out;

    float *bufA, *bufB, *bufT, *pooled, *counts, *stats, *ident;
    __nv_bfloat16 *h0, *h1, *wth, *wtl;
    int *rowptr, *cur, *eidx;
    cudaGetSymbolAddress((void**)&bufA,   g_bufA);
    cudaGetSymbolAddress((void**)&bufB,   g_bufB);
    cudaGetSymbolAddress((void**)&bufT,   g_bufT);
    cudaGetSymbolAddress((void**)&pooled, g_pooled);
    cudaGetSymbolAddress((void**)&counts, g_counts);
    cudaGetSymbolAddress((void**)&stats,  g_stats);
    cudaGetSymbolAddress((void**)&ident,  g_ident);
    cudaGetSymbolAddress((void**)&h0,     g_h0);
    cudaGetSymbolAddress((void**)&h1,     g_h1);
    cudaGetSymbolAddress((void**)&wth,    g_wth);
    cudaGetSymbolAddress((void**)&wtl,    g_wtl);
    cudaGetSymbolAddress((void**)&rowptr, g_rowptr);
    cudaGetSymbolAddress((void**)&cur,    g_cur);
    cudaGetSymbolAddress((void**)&eidx,   g_eidx);

    // ---- one-time per launch: weights, identity, CSR ----
    wsplit_kernel<<<(10 * NP * KP + 255) / 256, 256>>>(W1, W2, wth, wtl);
    init_ident_kernel<<<2, 256>>>(ident);
    cudaMemsetAsync(cur, 0, NN * sizeof(int), 0);
    hist_kernel<<<(EE + 255) / 256, 256>>>(ei, cur);
    scan_kernel<<<1, 1024>>>(cur, rowptr);
    fill_kernel<<<(EE + 255) / 256, 256>>>(ei, cur, eidx);

    dim3 pg(NGR, 3);
    pool_kernel<<<pg, 128>>>(x, ident, ident + DD, 0, batch, pooled, counts);

    const float* hcur = x;
    const float* csc = ident;        // current scale (identity for layer 0)
    const float* csh = ident + DD;   // current shift
    int crelu = 0;
    float* zb[2] = { bufA, bufB };
    const dim3 gemm_grid(NP / 64, (NN + 127) / 128);   // (5, 391)
    const int split_blocks = (NN * 80 + 255) / 256;
    const int agg_blocks = (NN * 32 + 255) / 256;      // one warp per node

    for (int i = 0; i < LL; i++) {
        float* z = zb[i & 1];

        // fused activate(prev BN) + aggregate + split
        agg_split_kernel<<<agg_blocks, 256>>>(hcur, csc, csh, crelu, rowptr, eidx, h0, h1);

        cudaMemsetAsync(stats, 0, 4 * DD * sizeof(float), 0);

        gemm_tc<<<gemm_grid, 256>>>(h0, h1,
                                    wth + (size_t)i * NP * KP, wtl + (size_t)i * NP * KP,
                                    b1 + i * DD, bufT, stats, stats + DD, NN);
        bn_prep_kernel<<<1, 320>>>(stats, stats + DD, g1 + i * DD, be1 + i * DD,
                                   stats + 4 * DD, stats + 5 * DD);
        bn_relu_split_kernel<<<split_blocks, 256>>>(bufT, stats + 4 * DD, stats + 5 * DD, h0, h1);

        gemm_tc<<<gemm_grid, 256>>>(h0, h1,
                                    wth + (size_t)(i + 5) * NP * KP, wtl + (size_t)(i + 5) * NP * KP,
                                    b2 + i * DD, z, stats + 2 * DD, stats + 3 * DD, NN);
        bn_prep_kernel<<<1, 320>>>(stats + 2 * DD, stats + 3 * DD, bng + i * DD, bnb + i * DD,
                                   stats + 6 * DD, stats + 7 * DD);

        // pool layer output with fused BN+ReLU (z stays pre-BN in memory)
        pool_kernel<<<pg, 128>>>(z, stats + 6 * DD, stats + 7 * DD, 1, batch,
                                 pooled + (size_t)(i + 1) * NGR * DD, nullptr);

        hcur = z; csc = stats + 6 * DD; csh = stats + 7 * DD; crelu = 1;
    }

    head_kernel<<<NGR, CC>>>(pooled, counts, fcW, fcb, out);
}

// round 7
// speedup vs baseline: 2.2561x; 1.0962x over previous
#include <cuda_runtime.h>
#include <cuda_fp16.h>
#include <cstdint>

#define NN 50000
#define DD 300
#define KP 320          // K padded to 10*32
#define NP 320          // N padded to 5*64
#define EE 400000
#define LL 5
#define CC 128
#define NGR 256
#define BN_EPS 1e-5f

typedef unsigned long long u64;

// ---------------- device scratch ----------------
__device__ float g_bufA[NN * DD];
__device__ float g_bufB[NN * DD];
__device__ float g_bufT[NN * DD];
__device__ __half g_h0[NN * KP];        // hi split of current GEMM input (fp16)
__device__ __half g_h1[NN * KP];        // lo split
__device__ __half g_wt[10 * NP * KP];   // transposed weight fp16: [w][n][k]
__device__ float g_pooled[(LL + 1) * NGR * DD];
__device__ float g_counts[NGR];
__device__ float g_stats[8 * DD];
__device__ float g_ident[2 * DD];       // [0..DD)=1, [DD..2DD)=0
__device__ int g_rowptr[NN + 1];
__device__ int g_cur[NN];
__device__ int g_eidx[EE];
__device__ int g_bsum[64];

// ---------------- PTX helpers (all arch-agnostic: sm_80+) ----------------
__device__ __forceinline__ uint32_t smem_u32(const void* p) {
    uint32_t a;
    asm("{ .reg .u64 t; cvta.to.shared.u64 t, %1; cvt.u32.u64 %0, t; }" : "=r"(a) : "l"(p));
    return a;
}
__device__ __forceinline__ void cpasync16(uint32_t dst, const void* src, int srcsize) {
    asm volatile("cp.async.cg.shared.global [%0], [%1], 16, %2;"
                 :: "r"(dst), "l"(src), "r"(srcsize) : "memory");
}
__device__ __forceinline__ void cp_commit() {
    asm volatile("cp.async.commit_group;" ::: "memory");
}
template<int N> __device__ __forceinline__ void cp_wait() {
    asm volatile("cp.async.wait_group %0;" :: "n"(N) : "memory");
}
__device__ __forceinline__ void ldsm4(uint32_t& r0, uint32_t& r1, uint32_t& r2, uint32_t& r3,
                                      uint32_t addr) {
    asm volatile("ldmatrix.sync.aligned.m8n8.x4.shared.b16 {%0,%1,%2,%3}, [%4];"
                 : "=r"(r0), "=r"(r1), "=r"(r2), "=r"(r3) : "r"(addr));
}
__device__ __forceinline__ void mma_f16(float* c, const uint32_t* a, const uint32_t* b) {
    asm volatile("mma.sync.aligned.m16n8k16.row.col.f32.f16.f16.f32 "
                 "{%0,%1,%2,%3}, {%4,%5,%6,%7}, {%8,%9}, {%0,%1,%2,%3};"
                 : "+f"(c[0]), "+f"(c[1]), "+f"(c[2]), "+f"(c[3])
                 : "r"(a[0]), "r"(a[1]), "r"(a[2]), "r"(a[3]), "r"(b[0]), "r"(b[1]));
}
__device__ __forceinline__ uint32_t tile_off(int row, int c) {
    return (uint32_t)(row * 64 + ((c ^ ((row >> 1) & 3)) << 4));
}

// ---------------- CSR build (parallel scan) ----------------
__global__ void hist_kernel(const int* __restrict__ ei, int* __restrict__ deg) {
    int e = blockIdx.x * blockDim.x + threadIdx.x;
    if (e < EE) atomicAdd(&deg[ei[EE + e]], 1);
}

__global__ void scan_sum_kernel(const int* __restrict__ deg, int* __restrict__ bsum) {
    __shared__ int sm[1024];
    int i = blockIdx.x * 1024 + threadIdx.x;
    sm[threadIdx.x] = (i < NN) ? deg[i] : 0;
    __syncthreads();
    for (int off = 512; off; off >>= 1) {
        if (threadIdx.x < off) sm[threadIdx.x] += sm[threadIdx.x + off];
        __syncthreads();
    }
    if (threadIdx.x == 0) bsum[blockIdx.x] = sm[0];
}

__global__ void scan_top_kernel(int* __restrict__ bsum, int nb) {
    __shared__ int sm[64];
    int t = threadIdx.x;
    int v = (t < nb) ? bsum[t] : 0;
    sm[t] = v;
    __syncthreads();
    for (int off = 1; off < 64; off <<= 1) {
        int u = (t >= off) ? sm[t - off] : 0;
        __syncthreads();
        sm[t] += u;
        __syncthreads();
    }
    if (t < nb) bsum[t] = sm[t] - v;   // exclusive block offsets
}

__global__ void scan_final_kernel(int* __restrict__ deg_cur, const int* __restrict__ bsum,
                                  int* __restrict__ rowptr) {
    __shared__ int sm[1024];
    int t = threadIdx.x;
    int i = blockIdx.x * 1024 + t;
    int v = (i < NN) ? deg_cur[i] : 0;
    sm[t] = v;
    __syncthreads();
    for (int off = 1; off < 1024; off <<= 1) {
        int u = (t >= off) ? sm[t - off] : 0;
        __syncthreads();
        sm[t] += u;
        __syncthreads();
    }
    int incl = sm[t] + bsum[blockIdx.x];
    if (i < NN) { rowptr[i + 1] = incl; deg_cur[i] = incl - v; }
    if (i == 0) rowptr[0] = 0;
}

__global__ void fill_kernel(const int* __restrict__ ei, int* __restrict__ cur,
                            int* __restrict__ eidx) {
    int e = blockIdx.x * blockDim.x + threadIdx.x;
    if (e >= EE) return;
    int pos = atomicAdd(&cur[ei[EE + e]], 1);
    eidx[pos] = ei[e];
}

__global__ void init_ident_kernel(float* __restrict__ ident) {
    int c = blockIdx.x * blockDim.x + threadIdx.x;
    if (c < DD) { ident[c] = 1.f; ident[DD + c] = 0.f; }
}

// ---------------- weight transpose -> fp16 ----------------
__global__ void wsplit_kernel(const float* __restrict__ W1, const float* __restrict__ W2,
                              __half* __restrict__ wt)
{
    int idx = blockIdx.x * blockDim.x + threadIdx.x;
    if (idx >= 10 * NP * KP) return;
    int w = idx / (NP * KP);
    int r = idx - w * NP * KP;
    int n = r / KP, k = r - n * KP;
    float v = 0.f;
    if (n < DD && k < DD)
        v = (w < 5) ? W1[(size_t)w * DD * DD + (size_t)k * DD + n]
                    : W2[(size_t)(w - 5) * DD * DD + (size_t)k * DD + n];
    wt[idx] = __float2half(v);
}

// ---------------- fused: BN/ReLU(on the fly) + GIN aggregate + fp16 hi/lo split ----------------
__global__ void __launch_bounds__(256)
agg_split_kernel(const float* __restrict__ h,
                 const float* __restrict__ scale, const float* __restrict__ shift, int do_relu,
                 const int* __restrict__ rowptr, const int* __restrict__ eidx,
                 __half* __restrict__ h0, __half* __restrict__ h1)
{
    int n = (blockIdx.x * 256 + threadIdx.x) >> 5;
    int lane = threadIdx.x & 31;
    if (n >= NN) return;
    int r0 = __ldg(&rowptr[n]), r1 = __ldg(&rowptr[n + 1]);
#pragma unroll
    for (int cb = 0; cb < KP; cb += 64) {
        int c0 = cb + lane, c1 = cb + 32 + lane;
        bool v0 = c0 < DD, v1 = c1 < DD;
        float s0 = v0 ? __ldg(&scale[c0]) : 0.f, t0 = v0 ? __ldg(&shift[c0]) : 0.f;
        float s1 = v1 ? __ldg(&scale[c1]) : 0.f, t1 = v1 ? __ldg(&shift[c1]) : 0.f;
        float a0 = 0.f, a1 = 0.f;
        if (v0) { float v = h[(size_t)n * DD + c0] * s0 + t0; a0 = do_relu ? fmaxf(v, 0.f) : v; }
        if (v1) { float v = h[(size_t)n * DD + c1] * s1 + t1; a1 = do_relu ? fmaxf(v, 0.f) : v; }
        for (int e = r0; e < r1; e++) {
            int s = __ldg(&eidx[e]);
            if (v0) { float v = __ldg(&h[(size_t)s * DD + c0]) * s0 + t0; a0 += do_relu ? fmaxf(v, 0.f) : v; }
            if (v1) { float v = __ldg(&h[(size_t)s * DD + c1]) * s1 + t1; a1 += do_relu ? fmaxf(v, 0.f) : v; }
        }
        __half hh0 = __float2half(a0);
        __half ll0 = __float2half(a0 - __half2float(hh0));
        __half hh1 = __float2half(a1);
        __half ll1 = __float2half(a1 - __half2float(hh1));
        h0[(size_t)n * KP + c0] = hh0; h1[(size_t)n * KP + c0] = ll0;
        h0[(size_t)n * KP + c1] = hh1; h1[(size_t)n * KP + c1] = ll1;
    }
}

// ---------------- BN apply + ReLU -> fp16 hi/lo split (mid-layer) ----------------
__global__ void bn_relu_split_kernel(const float* __restrict__ t,
                                     const float* __restrict__ scale, const float* __restrict__ shift,
                                     __half* __restrict__ h0, __half* __restrict__ h1)
{
    int idx = blockIdx.x * blockDim.x + threadIdx.x;
    if (idx >= NN * 80) return;
    int row = idx / 80, c4 = idx - row * 80;
    int c = c4 * 4;
    float f[4] = { 0.f, 0.f, 0.f, 0.f };
    if (c + 3 < DD) {
        float4 v = *reinterpret_cast<const float4*>(t + (size_t)row * DD + c);
        f[0] = fmaxf(v.x * scale[c] + shift[c], 0.f);
        f[1] = fmaxf(v.y * scale[c + 1] + shift[c + 1], 0.f);
        f[2] = fmaxf(v.z * scale[c + 2] + shift[c + 2], 0.f);
        f[3] = fmaxf(v.w * scale[c + 3] + shift[c + 3], 0.f);
    }
    ushort4 uh, ul;
    unsigned short* ph = &uh.x; unsigned short* pl = &ul.x;
#pragma unroll
    for (int tt = 0; tt < 4; tt++) {
        __half h = __float2half(f[tt]);
        __half l = __float2half(f[tt] - __half2float(h));
        ph[tt] = __half_as_ushort(h); pl[tt] = __half_as_ushort(l);
    }
    *reinterpret_cast<ushort4*>(h0 + (size_t)row * KP + c) = uh;
    *reinterpret_cast<ushort4*>(h1 + (size_t)row * KP + c) = ul;
}

// ---------------- fp16x2 mma.sync GEMM: out = A @ W + bias, fused BN stats ----------------
// A as hi/lo fp16 [M,KP]; W transposed fp16 [NP,KP] (= col-major B).
// Block 128x64, 8 warps (4x2), warp 32x32. K chunk 32, double-buffered cp.async.
// smem per stage: Ah 8K | Al 8K | B 4K = 20KB; 2 stages = 40KB.
#define ST_AH 0
#define ST_AL 8192
#define ST_B  16384
#define ST_SZ 20480

__global__ void __launch_bounds__(256)
gemm_tc(const __half* __restrict__ ah, const __half* __restrict__ al,
        const __half* __restrict__ bw,
        const float* __restrict__ bias, float* __restrict__ out,
        float* __restrict__ gsum, float* __restrict__ gsq, int M)
{
    __shared__ __align__(16) char smem[2 * ST_SZ];
    const uint32_t sb = smem_u32(smem);
    const int tid = threadIdx.x;
    const int lane = tid & 31;
    const int w = tid >> 5;
    const int wm = w >> 1, wn = w & 1;
    const int n0 = blockIdx.x * 64;
    const int m0 = blockIdx.y * 128;

    float acc[2][4][4];
#pragma unroll
    for (int mt = 0; mt < 2; mt++)
#pragma unroll
        for (int nt = 0; nt < 4; nt++)
#pragma unroll
            for (int q = 0; q < 4; q++) acc[mt][nt][q] = 0.f;

    const int ar0 = (tid * 2) >> 2, ac0 = (tid * 2) & 3;
    const int ar1 = (tid * 2 + 1) >> 2, ac1 = (tid * 2 + 1) & 3;
    const int br = tid >> 2, bc = tid & 3;
    const uint32_t dA0 = tile_off(ar0, ac0), dA1 = tile_off(ar1, ac1), dB = tile_off(br, bc);
    const int szA0 = (m0 + ar0 < M) ? 16 : 0;
    const int szA1 = (m0 + ar1 < M) ? 16 : 0;

#define LOAD_STAGE(kc, s) do {                                                        \
        int k0_ = (kc) * 32;                                                          \
        uint32_t base_ = sb + (s) * ST_SZ;                                            \
        cpasync16(base_ + ST_AH + dA0, ah + (size_t)(m0 + ar0) * KP + k0_ + ac0 * 8, szA0); \
        cpasync16(base_ + ST_AH + dA1, ah + (size_t)(m0 + ar1) * KP + k0_ + ac1 * 8, szA1); \
        cpasync16(base_ + ST_AL + dA0, al + (size_t)(m0 + ar0) * KP + k0_ + ac0 * 8, szA0); \
        cpasync16(base_ + ST_AL + dA1, al + (size_t)(m0 + ar1) * KP + k0_ + ac1 * 8, szA1); \
        cpasync16(base_ + ST_B + dB, bw + (size_t)(n0 + br) * KP + k0_ + bc * 8, 16);       \
        cp_commit();                                                                  \
    } while (0)

    LOAD_STAGE(0, 0);

    const int arow = wm * 32 + (lane & 7) + ((lane >> 3) & 1) * 8;
    const int acu = lane >> 4;
    const int brow = wn * 32 + (lane & 7) + ((lane >> 4) & 1) * 8;
    const int bcu = (lane >> 3) & 1;

    for (int kc = 0; kc < 10; kc++) {
        if (kc < 9) LOAD_STAGE(kc + 1, (kc + 1) & 1);
        if (kc < 9) cp_wait<1>(); else cp_wait<0>();
        __syncthreads();

        const uint32_t base = sb + (kc & 1) * ST_SZ;
#pragma unroll
        for (int k16 = 0; k16 < 2; k16++) {
            uint32_t Ah[2][4], Al[2][4], Bw[2][4];
#pragma unroll
            for (int mt = 0; mt < 2; mt++) {
                uint32_t oa = tile_off(arow + mt * 16, acu + 2 * k16);
                ldsm4(Ah[mt][0], Ah[mt][1], Ah[mt][2], Ah[mt][3], base + ST_AH + oa);
                ldsm4(Al[mt][0], Al[mt][1], Al[mt][2], Al[mt][3], base + ST_AL + oa);
            }
#pragma unroll
            for (int g = 0; g < 2; g++) {
                uint32_t ob = tile_off(brow + g * 16, bcu + 2 * k16);
                ldsm4(Bw[g][0], Bw[g][1], Bw[g][2], Bw[g][3], base + ST_B + ob);
            }
#pragma unroll
            for (int mt = 0; mt < 2; mt++)
#pragma unroll
                for (int g = 0; g < 2; g++)
#pragma unroll
                    for (int sub = 0; sub < 2; sub++) {
                        int nt = g * 2 + sub;
                        mma_f16(acc[mt][nt], Ah[mt], &Bw[g][sub * 2]);
                        mma_f16(acc[mt][nt], Al[mt], &Bw[g][sub * 2]);
                    }
        }
        __syncthreads();
    }

    float* ssum = reinterpret_cast<float*>(smem);
    float* ssq  = reinterpret_cast<float*>(smem + 256);
    if (tid < 64) { ssum[tid] = 0.f; ssq[tid] = 0.f; }
    __syncthreads();

    float ls[8], lq[8];
#pragma unroll
    for (int j = 0; j < 8; j++) { ls[j] = 0.f; lq[j] = 0.f; }

#pragma unroll
    for (int nt = 0; nt < 4; nt++) {
        int cl0 = wn * 32 + nt * 8 + 2 * (lane & 3);
        int gc0 = n0 + cl0;
        float bb0 = (gc0 < DD) ? bias[gc0] : 0.f;
        float bb1 = (gc0 + 1 < DD) ? bias[gc0 + 1] : 0.f;
#pragma unroll
        for (int mt = 0; mt < 2; mt++) {
            int r0 = m0 + wm * 32 + mt * 16 + (lane >> 2);
            int r1 = r0 + 8;
            float v0 = acc[mt][nt][0] + bb0;
            float v1 = acc[mt][nt][1] + bb1;
            float v2 = acc[mt][nt][2] + bb0;
            float v3 = acc[mt][nt][3] + bb1;
            if (r0 < M && gc0 < DD)
                *reinterpret_cast<float2*>(out + (size_t)r0 * DD + gc0) = make_float2(v0, v1);
            if (r1 < M && gc0 < DD)
                *reinterpret_cast<float2*>(out + (size_t)r1 * DD + gc0) = make_float2(v2, v3);
            float s0 = (r0 < M) ? v0 : 0.f, s2 = (r1 < M) ? v2 : 0.f;
            float s1 = (r0 < M) ? v1 : 0.f, s3 = (r1 < M) ? v3 : 0.f;
            ls[nt * 2]     += s0 + s2;  lq[nt * 2]     += s0 * s0 + s2 * s2;
            ls[nt * 2 + 1] += s1 + s3;  lq[nt * 2 + 1] += s1 * s1 + s3 * s3;
        }
    }
#pragma unroll
    for (int nt = 0; nt < 4; nt++) {
        int cl0 = wn * 32 + nt * 8 + 2 * (lane & 3);
        atomicAdd(&ssum[cl0], ls[nt * 2]);     atomicAdd(&ssq[cl0], lq[nt * 2]);
        atomicAdd(&ssum[cl0 + 1], ls[nt * 2 + 1]); atomicAdd(&ssq[cl0 + 1], lq[nt * 2 + 1]);
    }
    __syncthreads();
    if (tid < 64) {
        int n = n0 + tid;
        if (n < DD) { atomicAdd(gsum + n, ssum[tid]); atomicAdd(gsq + n, ssq[tid]); }
    }
#undef LOAD_STAGE
}

// ---------------- BN prep ----------------
__global__ void bn_prep_kernel(const float* __restrict__ gsum, const float* __restrict__ gsq,
                               const float* __restrict__ gamma, const float* __restrict__ beta,
                               float* __restrict__ scale, float* __restrict__ shift)
{
    int c = blockIdx.x * blockDim.x + threadIdx.x;
    if (c >= DD) return;
    const float invN = 1.0f / (float)NN;
    float mu = gsum[c] * invN;
    float var = gsq[c] * invN - mu * mu;
    float rs = rsqrtf(var + BN_EPS);
    float sc = rs * gamma[c];
    scale[c] = sc;
    shift[c] = beta[c] - mu * sc;
}

// ---------------- per-graph pooling with fused BN/ReLU ----------------
__global__ void pool_kernel(const float* __restrict__ h,
                            const float* __restrict__ scale, const float* __restrict__ shift,
                            int do_relu, const int* __restrict__ batch,
                            float* __restrict__ pooled, float* __restrict__ counts)
{
    int g = blockIdx.x;
    int lo = 0, hi = NN;
    while (lo < hi) { int mid = (lo + hi) >> 1; if (batch[mid] < g) lo = mid + 1; else hi = mid; }
    int s = lo;
    lo = s; hi = NN;
    while (lo < hi) { int mid = (lo + hi) >> 1; if (batch[mid] < g + 1) lo = mid + 1; else hi = mid; }
    int e = lo;
    if (counts && threadIdx.x == 0 && blockIdx.y == 0) counts[g] = (float)(e - s);
    int c = blockIdx.y * 100 + threadIdx.x;
    if (threadIdx.x < 100) {
        float sc = scale[c], sh = shift[c];
        float acc = 0.f;
        for (int n = s; n < e; n++) {
            float v = h[(size_t)n * DD + c] * sc + sh;
            if (do_relu) v = fmaxf(v, 0.f);
            acc += v;
        }
        pooled[(size_t)g * DD + c] = acc;
    }
}

// ---------------- readout heads ----------------
__global__ void head_kernel(const float* __restrict__ pooled, const float* __restrict__ counts,
                            const float* __restrict__ fcW, const float* __restrict__ fcb,
                            float* __restrict__ out)
{
    int g = blockIdx.x;
    int c = threadIdx.x;
    float inv = 1.0f / fmaxf(counts[g], 1.0f);
    float acc = 0.f;
#pragma unroll
    for (int i = 0; i <= LL; i++) {
        const float* p = pooled + ((size_t)i * NGR + g) * DD;
        const float* Wp = fcW + (size_t)i * DD * CC + c;
        float s = 0.f;
#pragma unroll 4
        for (int k = 0; k < DD; k++) s += __ldg(&p[k]) * __ldg(&Wp[(size_t)k * CC]);
        acc += s * inv + __ldg(&fcb[i * CC + c]);
    }
    out[(size_t)g * CC + c] = acc;
}

// ---------------- launch ----------------
extern "C" void kernel_launch(void* const* d_in, const int* in_sizes, int n_in,
                              void* d_out, int out_size)
{
    int ix, iei, ibatch, iW1, ib1, ig1, ibe1, iW2, ib2, ibng, ibnb, ifcW, ifcb;
    if (in_sizes[0] == NN) {  // alphabetical
        ibatch = 0; ibnb = 1; ibng = 2; iei = 3; ifcW = 4; ifcb = 5;
        iW1 = 6; iW2 = 7; ib1 = 8; ib2 = 9; ibe1 = 10; ig1 = 11; ix = 12;
    } else {                  // insertion order
        ix = 0; iei = 1; ibatch = 2; iW1 = 3; ib1 = 4; ig1 = 5; ibe1 = 6;
        iW2 = 7; ib2 = 8; ibng = 9; ibnb = 10; ifcW = 11; ifcb = 12;
    }
    const float* x     = (const float*)d_in[ix];
    const int*   ei    = (const int*)d_in[iei];
    const int*   batch = (const int*)d_in[ibatch];
    const float* W1    = (const float*)d_in[iW1];
    const float* b1    = (const float*)d_in[ib1];
    const float* g1    = (const float*)d_in[ig1];
    const float* be1   = (const float*)d_in[ibe1];
    const float* W2    = (const float*)d_in[iW2];
    const float* b2    = (const float*)d_in[ib2];
    const float* bng   = (const float*)d_in[ibng];
    const float* bnb   = (const float*)d_in[ibnb];
    const float* fcW   = (const float*)d_in[ifcW];
    const float* fcb   = (const float*)d_in[ifcb];
    float* out = (float*)d_out;

    float *bufA, *bufB, *bufT, *pooled, *counts, *stats, *ident;
    __half *h0, *h1, *wt;
    int *rowptr, *cur, *eidx, *bsum;
    cudaGetSymbolAddress((void**)&bufA,   g_bufA);
    cudaGetSymbolAddress((void**)&bufB,   g_bufB);
    cudaGetSymbolAddress((void**)&bufT,   g_bufT);
    cudaGetSymbolAddress((void**)&pooled, g_pooled);
    cudaGetSymbolAddress((void**)&counts, g_counts);
    cudaGetSymbolAddress((void**)&stats,  g_stats);
    cudaGetSymbolAddress((void**)&ident,  g_ident);
    cudaGetSymbolAddress((void**)&h0,     g_h0);
    cudaGetSymbolAddress((void**)&h1,     g_h1);
    cudaGetSymbolAddress((void**)&wt,     g_wt);
    cudaGetSymbolAddress((void**)&rowptr, g_rowptr);
    cudaGetSymbolAddress((void**)&cur,    g_cur);
    cudaGetSymbolAddress((void**)&eidx,   g_eidx);
    cudaGetSymbolAddress((void**)&bsum,   g_bsum);

    // ---- one-time per launch: weights, identity, CSR ----
    const int NB = (NN + 1023) / 1024;   // 49
    wsplit_kernel<<<(10 * NP * KP + 255) / 256, 256>>>(W1, W2, wt);
    init_ident_kernel<<<2, 256>>>(ident);
    cudaMemsetAsync(cur, 0, NN * sizeof(int), 0);
    hist_kernel<<<(EE + 255) / 256, 256>>>(ei, cur);
    scan_sum_kernel<<<NB, 1024>>>(cur, bsum);
    scan_top_kernel<<<1, 64>>>(bsum, NB);
    scan_final_kernel<<<NB, 1024>>>(cur, bsum, rowptr);
    fill_kernel<<<(EE + 255) / 256, 256>>>(ei, cur, eidx);

    dim3 pg(NGR, 3);
    pool_kernel<<<pg, 128>>>(x, ident, ident + DD, 0, batch, pooled, counts);

    const float* hcur = x;
    const float* csc = ident;
    const float* csh = ident + DD;
    int crelu = 0;
    float* zb[2] = { bufA, bufB };
    const dim3 gemm_grid(NP / 64, (NN + 127) / 128);   // (5, 391)
    const int split_blocks = (NN * 80 + 255) / 256;
    const int agg_blocks = (NN * 32 + 255) / 256;

    for (int i = 0; i < LL; i++) {
        float* z = zb[i & 1];

        agg_split_kernel<<<agg_blocks, 256>>>(hcur, csc, csh, crelu, rowptr, eidx, h0, h1);

        cudaMemsetAsync(stats, 0, 4 * DD * sizeof(float), 0);

        gemm_tc<<<gemm_grid, 256>>>(h0, h1, wt + (size_t)i * NP * KP,
                                    b1 + i * DD, bufT, stats, stats + DD, NN);
        bn_prep_kernel<<<1, 320>>>(stats, stats + DD, g1 + i * DD, be1 + i * DD,
                                   stats + 4 * DD, stats + 5 * DD);
        bn_relu_split_kernel<<<split_blocks, 256>>>(bufT, stats + 4 * DD, stats + 5 * DD, h0, h1);

        gemm_tc<<<gemm_grid, 256>>>(h0, h1, wt + (size_t)(i + 5) * NP * KP,
                                    b2 + i * DD, z, stats + 2 * DD, stats + 3 * DD, NN);
        bn_prep_kernel<<<1, 320>>>(stats + 2 * DD, stats + 3 * DD, bng + i * DD, bnb + i * DD,
                                   stats + 6 * DD, stats + 7 * DD);

        pool_kernel<<<pg, 128>>>(z, stats + 6 * DD, stats + 7 * DD, 1, batch,
                                 pooled + (size_t)(i + 1) * NGR * DD, nullptr);

        hcur = z; csc = stats + 6 * DD; csh = stats + 7 * DD; crelu = 1;
    }

    head_kernel<<<NGR, CC>>>(pooled, counts, fcW, fcb, out);
}

// round 8
// speedup vs baseline: 3.0983x; 1.3733x over previous
#include <cuda_runtime.h>
#include <cuda_fp16.h>
#include <cstdint>

#define NN 50000
#define DD 300
#define KP 320          // K padded to 10*32
#define NP 320          // N padded to 5*64
#define EE 400000
#define LL 5
#define CC 128
#define NGR 256
#define BN_EPS 1e-5f

typedef unsigned long long u64;

// ---------------- device scratch ----------------
__device__ float g_bufA[NN * DD];
__device__ float g_bufB[NN * DD];
__device__ float g_bufT[NN * DD];
__device__ __half g_h0[NN * KP];        // fp16 GEMM input
__device__ __half g_wt[10 * NP * KP];   // transposed weight fp16: [w][n][k]
__device__ float g_pooled[(LL + 1) * NGR * DD];
__device__ float g_counts[NGR];
__device__ float g_stats[8 * DD];
__device__ float g_ident[2 * DD];       // [0..DD)=1, [DD..2DD)=0
__device__ int g_rowptr[NN + 1];
__device__ int g_cur[NN];
__device__ int g_eidx[EE];
__device__ int g_bsum[64];

// ---------------- PTX helpers (all arch-agnostic: sm_80+) ----------------
__device__ __forceinline__ uint32_t smem_u32(const void* p) {
    uint32_t a;
    asm("{ .reg .u64 t; cvta.to.shared.u64 t, %1; cvt.u32.u64 %0, t; }" : "=r"(a) : "l"(p));
    return a;
}
__device__ __forceinline__ void cpasync16(uint32_t dst, const void* src, int srcsize) {
    asm volatile("cp.async.cg.shared.global [%0], [%1], 16, %2;"
                 :: "r"(dst), "l"(src), "r"(srcsize) : "memory");
}
__device__ __forceinline__ void cp_commit() {
    asm volatile("cp.async.commit_group;" ::: "memory");
}
template<int N> __device__ __forceinline__ void cp_wait() {
    asm volatile("cp.async.wait_group %0;" :: "n"(N) : "memory");
}
__device__ __forceinline__ void ldsm4(uint32_t& r0, uint32_t& r1, uint32_t& r2, uint32_t& r3,
                                      uint32_t addr) {
    asm volatile("ldmatrix.sync.aligned.m8n8.x4.shared.b16 {%0,%1,%2,%3}, [%4];"
                 : "=r"(r0), "=r"(r1), "=r"(r2), "=r"(r3) : "r"(addr));
}
__device__ __forceinline__ void mma_f16(float* c, const uint32_t* a, const uint32_t* b) {
    asm volatile("mma.sync.aligned.m16n8k16.row.col.f32.f16.f16.f32 "
                 "{%0,%1,%2,%3}, {%4,%5,%6,%7}, {%8,%9}, {%0,%1,%2,%3};"
                 : "+f"(c[0]), "+f"(c[1]), "+f"(c[2]), "+f"(c[3])
                 : "r"(a[0]), "r"(a[1]), "r"(a[2]), "r"(a[3]), "r"(b[0]), "r"(b[1]));
}
__device__ __forceinline__ uint32_t tile_off(int row, int c) {
    return (uint32_t)(row * 64 + ((c ^ ((row >> 1) & 3)) << 4));
}

// ---------------- CSR build (parallel scan) ----------------
__global__ void hist_kernel(const int* __restrict__ ei, int* __restrict__ deg) {
    int e = blockIdx.x * blockDim.x + threadIdx.x;
    if (e < EE) atomicAdd(&deg[ei[EE + e]], 1);
}

__global__ void scan_sum_kernel(const int* __restrict__ deg, int* __restrict__ bsum) {
    __shared__ int sm[1024];
    int i = blockIdx.x * 1024 + threadIdx.x;
    sm[threadIdx.x] = (i < NN) ? deg[i] : 0;
    __syncthreads();
    for (int off = 512; off; off >>= 1) {
        if (threadIdx.x < off) sm[threadIdx.x] += sm[threadIdx.x + off];
        __syncthreads();
    }
    if (threadIdx.x == 0) bsum[blockIdx.x] = sm[0];
}

__global__ void scan_top_kernel(int* __restrict__ bsum, int nb) {
    __shared__ int sm[64];
    int t = threadIdx.x;
    int v = (t < nb) ? bsum[t] : 0;
    sm[t] = v;
    __syncthreads();
    for (int off = 1; off < 64; off <<= 1) {
        int u = (t >= off) ? sm[t - off] : 0;
        __syncthreads();
        sm[t] += u;
        __syncthreads();
    }
    if (t < nb) bsum[t] = sm[t] - v;   // exclusive block offsets
}

__global__ void scan_final_kernel(int* __restrict__ deg_cur, const int* __restrict__ bsum,
                                  int* __restrict__ rowptr) {
    __shared__ int sm[1024];
    int t = threadIdx.x;
    int i = blockIdx.x * 1024 + t;
    int v = (i < NN) ? deg_cur[i] : 0;
    sm[t] = v;
    __syncthreads();
    for (int off = 1; off < 1024; off <<= 1) {
        int u = (t >= off) ? sm[t - off] : 0;
        __syncthreads();
        sm[t] += u;
        __syncthreads();
    }
    int incl = sm[t] + bsum[blockIdx.x];
    if (i < NN) { rowptr[i + 1] = incl; deg_cur[i] = incl - v; }
    if (i == 0) rowptr[0] = 0;
}

__global__ void fill_kernel(const int* __restrict__ ei, int* __restrict__ cur,
                            int* __restrict__ eidx) {
    int e = blockIdx.x * blockDim.x + threadIdx.x;
    if (e >= EE) return;
    int pos = atomicAdd(&cur[ei[EE + e]], 1);
    eidx[pos] = ei[e];
}

__global__ void init_ident_kernel(float* __restrict__ ident) {
    int c = blockIdx.x * blockDim.x + threadIdx.x;
    if (c < DD) { ident[c] = 1.f; ident[DD + c] = 0.f; }
}

// ---------------- weight transpose -> fp16 ----------------
__global__ void wsplit_kernel(const float* __restrict__ W1, const float* __restrict__ W2,
                              __half* __restrict__ wt)
{
    int idx = blockIdx.x * blockDim.x + threadIdx.x;
    if (idx >= 10 * NP * KP) return;
    int w = idx / (NP * KP);
    int r = idx - w * NP * KP;
    int n = r / KP, k = r - n * KP;
    float v = 0.f;
    if (n < DD && k < DD)
        v = (w < 5) ? W1[(size_t)w * DD * DD + (size_t)k * DD + n]
                    : W2[(size_t)(w - 5) * DD * DD + (size_t)k * DD + n];
    wt[idx] = __float2half(v);
}

// ---------------- fused: BN/ReLU(on the fly) + GIN aggregate -> fp16 ----------------
__global__ void __launch_bounds__(256)
agg_split_kernel(const float* __restrict__ h,
                 const float* __restrict__ scale, const float* __restrict__ shift, int do_relu,
                 const int* __restrict__ rowptr, const int* __restrict__ eidx,
                 __half* __restrict__ h0)
{
    int n = (blockIdx.x * 256 + threadIdx.x) >> 5;
    int lane = threadIdx.x & 31;
    if (n >= NN) return;
    int r0 = __ldg(&rowptr[n]), r1 = __ldg(&rowptr[n + 1]);
#pragma unroll
    for (int cb = 0; cb < KP; cb += 64) {
        int c0 = cb + lane, c1 = cb + 32 + lane;
        bool v0 = c0 < DD, v1 = c1 < DD;
        float s0 = v0 ? __ldg(&scale[c0]) : 0.f, t0 = v0 ? __ldg(&shift[c0]) : 0.f;
        float s1 = v1 ? __ldg(&scale[c1]) : 0.f, t1 = v1 ? __ldg(&shift[c1]) : 0.f;
        float a0 = 0.f, a1 = 0.f;
        if (v0) { float v = h[(size_t)n * DD + c0] * s0 + t0; a0 = do_relu ? fmaxf(v, 0.f) : v; }
        if (v1) { float v = h[(size_t)n * DD + c1] * s1 + t1; a1 = do_relu ? fmaxf(v, 0.f) : v; }
        for (int e = r0; e < r1; e++) {
            int s = __ldg(&eidx[e]);
            if (v0) { float v = __ldg(&h[(size_t)s * DD + c0]) * s0 + t0; a0 += do_relu ? fmaxf(v, 0.f) : v; }
            if (v1) { float v = __ldg(&h[(size_t)s * DD + c1]) * s1 + t1; a1 += do_relu ? fmaxf(v, 0.f) : v; }
        }
        h0[(size_t)n * KP + c0] = __float2half(a0);
        h0[(size_t)n * KP + c1] = __float2half(a1);
    }
}

// ---------------- BN apply + ReLU -> fp16 (mid-layer) ----------------
__global__ void bn_relu_split_kernel(const float* __restrict__ t,
                                     const float* __restrict__ scale, const float* __restrict__ shift,
                                     __half* __restrict__ h0)
{
    int idx = blockIdx.x * blockDim.x + threadIdx.x;
    if (idx >= NN * 80) return;
    int row = idx / 80, c4 = idx - row * 80;
    int c = c4 * 4;
    float f[4] = { 0.f, 0.f, 0.f, 0.f };
    if (c + 3 < DD) {
        float4 v = *reinterpret_cast<const float4*>(t + (size_t)row * DD + c);
        f[0] = fmaxf(v.x * scale[c] + shift[c], 0.f);
        f[1] = fmaxf(v.y * scale[c + 1] + shift[c + 1], 0.f);
        f[2] = fmaxf(v.z * scale[c + 2] + shift[c + 2], 0.f);
        f[3] = fmaxf(v.w * scale[c + 3] + shift[c + 3], 0.f);
    }
    ushort4 uh;
    unsigned short* ph = &uh.x;
#pragma unroll
    for (int tt = 0; tt < 4; tt++) ph[tt] = __half_as_ushort(__float2half(f[tt]));
    *reinterpret_cast<ushort4*>(h0 + (size_t)row * KP + c) = uh;
}

// ---------------- fp16 mma.sync GEMM: out = A @ W + bias, fused BN stats ----------------
// A fp16 [M,KP]; W transposed fp16 [NP,KP] (= col-major B).
// Block 128x64, 8 warps (4x2), warp 32x32. K chunk 32, double-buffered cp.async.
// smem per stage: A 8K | B 4K = 12KB; 2 stages = 24KB.
#define ST_A 0
#define ST_B 8192
#define ST_SZ 12288

__global__ void __launch_bounds__(256)
gemm_tc(const __half* __restrict__ ah, const __half* __restrict__ bw,
        const float* __restrict__ bias, float* __restrict__ out,
        float* __restrict__ gsum, float* __restrict__ gsq, int M)
{
    __shared__ __align__(16) char smem[2 * ST_SZ];
    const uint32_t sb = smem_u32(smem);
    const int tid = threadIdx.x;
    const int lane = tid & 31;
    const int w = tid >> 5;
    const int wm = w >> 1, wn = w & 1;
    const int n0 = blockIdx.x * 64;
    const int m0 = blockIdx.y * 128;

    float acc[2][4][4];
#pragma unroll
    for (int mt = 0; mt < 2; mt++)
#pragma unroll
        for (int nt = 0; nt < 4; nt++)
#pragma unroll
            for (int q = 0; q < 4; q++) acc[mt][nt][q] = 0.f;

    const int ar0 = (tid * 2) >> 2, ac0 = (tid * 2) & 3;
    const int ar1 = (tid * 2 + 1) >> 2, ac1 = (tid * 2 + 1) & 3;
    const int br = tid >> 2, bc = tid & 3;
    const uint32_t dA0 = tile_off(ar0, ac0), dA1 = tile_off(ar1, ac1), dB = tile_off(br, bc);
    const int szA0 = (m0 + ar0 < M) ? 16 : 0;
    const int szA1 = (m0 + ar1 < M) ? 16 : 0;

#define LOAD_STAGE(kc, s) do {                                                        \
        int k0_ = (kc) * 32;                                                          \
        uint32_t base_ = sb + (s) * ST_SZ;                                            \
        cpasync16(base_ + ST_A + dA0, ah + (size_t)(m0 + ar0) * KP + k0_ + ac0 * 8, szA0); \
        cpasync16(base_ + ST_A + dA1, ah + (size_t)(m0 + ar1) * KP + k0_ + ac1 * 8, szA1); \
        cpasync16(base_ + ST_B + dB, bw + (size_t)(n0 + br) * KP + k0_ + bc * 8, 16);       \
        cp_commit();                                                                  \
    } while (0)

    LOAD_STAGE(0, 0);

    const int arow = wm * 32 + (lane & 7) + ((lane >> 3) & 1) * 8;
    const int acu = lane >> 4;
    const int brow = wn * 32 + (lane & 7) + ((lane >> 4) & 1) * 8;
    const int bcu = (lane >> 3) & 1;

    for (int kc = 0; kc < 10; kc++) {
        if (kc < 9) LOAD_STAGE(kc + 1, (kc + 1) & 1);
        if (kc < 9) cp_wait<1>(); else cp_wait<0>();
        __syncthreads();

        const uint32_t base = sb + (kc & 1) * ST_SZ;
#pragma unroll
        for (int k16 = 0; k16 < 2; k16++) {
            uint32_t Ah[2][4], Bw[2][4];
#pragma unroll
            for (int mt = 0; mt < 2; mt++) {
                uint32_t oa = tile_off(arow + mt * 16, acu + 2 * k16);
                ldsm4(Ah[mt][0], Ah[mt][1], Ah[mt][2], Ah[mt][3], base + ST_A + oa);
            }
#pragma unroll
            for (int g = 0; g < 2; g++) {
                uint32_t ob = tile_off(brow + g * 16, bcu + 2 * k16);
                ldsm4(Bw[g][0], Bw[g][1], Bw[g][2], Bw[g][3], base + ST_B + ob);
            }
#pragma unroll
            for (int mt = 0; mt < 2; mt++)
#pragma unroll
                for (int g = 0; g < 2; g++)
#pragma unroll
                    for (int sub = 0; sub < 2; sub++)
                        mma_f16(acc[mt][g * 2 + sub], Ah[mt], &Bw[g][sub * 2]);
        }
        __syncthreads();
    }

    float* ssum = reinterpret_cast<float*>(smem);
    float* ssq  = reinterpret_cast<float*>(smem + 256);
    if (tid < 64) { ssum[tid] = 0.f; ssq[tid] = 0.f; }
    __syncthreads();

    float ls[8], lq[8];
#pragma unroll
    for (int j = 0; j < 8; j++) { ls[j] = 0.f; lq[j] = 0.f; }

#pragma unroll
    for (int nt = 0; nt < 4; nt++) {
        int cl0 = wn * 32 + nt * 8 + 2 * (lane & 3);
        int gc0 = n0 + cl0;
        float bb0 = (gc0 < DD) ? bias[gc0] : 0.f;
        float bb1 = (gc0 + 1 < DD) ? bias[gc0 + 1] : 0.f;
#pragma unroll
        for (int mt = 0; mt < 2; mt++) {
            int r0 = m0 + wm * 32 + mt * 16 + (lane >> 2);
            int r1 = r0 + 8;
            float v0 = acc[mt][nt][0] + bb0;
            float v1 = acc[mt][nt][1] + bb1;
            float v2 = acc[mt][nt][2] + bb0;
            float v3 = acc[mt][nt][3] + bb1;
            if (r0 < M && gc0 < DD)
                *reinterpret_cast<float2*>(out + (size_t)r0 * DD + gc0) = make_float2(v0, v1);
            if (r1 < M && gc0 < DD)
                *reinterpret_cast<float2*>(out + (size_t)r1 * DD + gc0) = make_float2(v2, v3);
            float s0 = (r0 < M) ? v0 : 0.f, s2 = (r1 < M) ? v2 : 0.f;
            float s1 = (r0 < M) ? v1 : 0.f, s3 = (r1 < M) ? v3 : 0.f;
            ls[nt * 2]     += s0 + s2;  lq[nt * 2]     += s0 * s0 + s2 * s2;
            ls[nt * 2 + 1] += s1 + s3;  lq[nt * 2 + 1] += s1 * s1 + s3 * s3;
        }
    }
#pragma unroll
    for (int nt = 0; nt < 4; nt++) {
        int cl0 = wn * 32 + nt * 8 + 2 * (lane & 3);
        atomicAdd(&ssum[cl0], ls[nt * 2]);     atomicAdd(&ssq[cl0], lq[nt * 2]);
        atomicAdd(&ssum[cl0 + 1], ls[nt * 2 + 1]); atomicAdd(&ssq[cl0 + 1], lq[nt * 2 + 1]);
    }
    __syncthreads();
    if (tid < 64) {
        int n = n0 + tid;
        if (n < DD) { atomicAdd(gsum + n, ssum[tid]); atomicAdd(gsq + n, ssq[tid]); }
    }
#undef LOAD_STAGE
}

// ---------------- BN prep ----------------
__global__ void bn_prep_kernel(const float* __restrict__ gsum, const float* __restrict__ gsq,
                               const float* __restrict__ gamma, const float* __restrict__ beta,
                               float* __restrict__ scale, float* __restrict__ shift)
{
    int c = blockIdx.x * blockDim.x + threadIdx.x;
    if (c >= DD) return;
    const float invN = 1.0f / (float)NN;
    float mu = gsum[c] * invN;
    float var = gsq[c] * invN - mu * mu;
    float rs = rsqrtf(var + BN_EPS);
    float sc = rs * gamma[c];
    scale[c] = sc;
    shift[c] = beta[c] - mu * sc;
}

// ---------------- per-graph pooling with fused BN/ReLU ----------------
__global__ void pool_kernel(const float* __restrict__ h,
                            const float* __restrict__ scale, const float* __restrict__ shift,
                            int do_relu, const int* __restrict__ batch,
                            float* __restrict__ pooled, float* __restrict__ counts)
{
    int g = blockIdx.x;
    int lo = 0, hi = NN;
    while (lo < hi) { int mid = (lo + hi) >> 1; if (batch[mid] < g) lo = mid + 1; else hi = mid; }
    int s = lo;
    lo = s; hi = NN;
    while (lo < hi) { int mid = (lo + hi) >> 1; if (batch[mid] < g + 1) lo = mid + 1; else hi = mid; }
    int e = lo;
    if (counts && threadIdx.x == 0 && blockIdx.y == 0) counts[g] = (float)(e - s);
    int c = blockIdx.y * 100 + threadIdx.x;
    if (threadIdx.x < 100) {
        float sc = scale[c], sh = shift[c];
        float acc = 0.f;
        for (int n = s; n < e; n++) {
            float v = h[(size_t)n * DD + c] * sc + sh;
            if (do_relu) v = fmaxf(v, 0.f);
            acc += v;
        }
        pooled[(size_t)g * DD + c] = acc;
    }
}

// ---------------- readout heads ----------------
__global__ void head_kernel(const float* __restrict__ pooled, const float* __restrict__ counts,
                            const float* __restrict__ fcW, const float* __restrict__ fcb,
                            float* __restrict__ out)
{
    int g = blockIdx.x;
    int c = threadIdx.x;
    float inv = 1.0f / fmaxf(counts[g], 1.0f);
    float acc = 0.f;
#pragma unroll
    for (int i = 0; i <= LL; i++) {
        const float* p = pooled + ((size_t)i * NGR + g) * DD;
        const float* Wp = fcW + (size_t)i * DD * CC + c;
        float s = 0.f;
#pragma unroll 4
        for (int k = 0; k < DD; k++) s += __ldg(&p[k]) * __ldg(&Wp[(size_t)k * CC]);
        acc += s * inv + __ldg(&fcb[i * CC + c]);
    }
    out[(size_t)g * CC + c] = acc;
}

// ---------------- launch ----------------
extern "C" void kernel_launch(void* const* d_in, const int* in_sizes, int n_in,
                              void* d_out, int out_size)
{
    int ix, iei, ibatch, iW1, ib1, ig1, ibe1, iW2, ib2, ibng, ibnb, ifcW, ifcb;
    if (in_sizes[0] == NN) {  // alphabetical
        ibatch = 0; ibnb = 1; ibng = 2; iei = 3; ifcW = 4; ifcb = 5;
        iW1 = 6; iW2 = 7; ib1 = 8; ib2 = 9; ibe1 = 10; ig1 = 11; ix = 12;
    } else {                  // insertion order
        ix = 0; iei = 1; ibatch = 2; iW1 = 3; ib1 = 4; ig1 = 5; ibe1 = 6;
        iW2 = 7; ib2 = 8; ibng = 9; ibnb = 10; ifcW = 11; ifcb = 12;
    }
    const float* x     = (const float*)d_in[ix];
    const int*   ei    = (const int*)d_in[iei];
    const int*   batch = (const int*)d_in[ibatch];
    const float* W1    = (const float*)d_in[iW1];
    const float* b1    = (const float*)d_in[ib1];
    const float* g1    = (const float*)d_in[ig1];
    const float* be1   = (const float*)d_in[ibe1];
    const float* W2    = (const float*)d_in[iW2];
    const float* b2    = (const float*)d_in[ib2];
    const float* bng   = (const float*)d_in[ibng];
    const float* bnb   = (const float*)d_in[ibnb];
    const float* fcW   = (const float*)d_in[ifcW];
    const float* fcb   = (const float*)d_in[ifcb];
    float* out = (float*)d_out;

    float *bufA, *bufB, *bufT, *pooled, *counts, *stats, *ident;
    __half *h0, *wt;
    int *rowptr, *cur, *eidx, *bsum;
    cudaGetSymbolAddress((void**)&bufA,   g_bufA);
    cudaGetSymbolAddress((void**)&bufB,   g_bufB);
    cudaGetSymbolAddress((void**)&bufT,   g_bufT);
    cudaGetSymbolAddress((void**)&pooled, g_pooled);
    cudaGetSymbolAddress((void**)&counts, g_counts);
    cudaGetSymbolAddress((void**)&stats,  g_stats);
    cudaGetSymbolAddress((void**)&ident,  g_ident);
    cudaGetSymbolAddress((void**)&h0,     g_h0);
    cudaGetSymbolAddress((void**)&wt,     g_wt);
    cudaGetSymbolAddress((void**)&rowptr, g_rowptr);
    cudaGetSymbolAddress((void**)&cur,    g_cur);
    cudaGetSymbolAddress((void**)&eidx,   g_eidx);
    cudaGetSymbolAddress((void**)&bsum,   g_bsum);

    // ---- one-time per launch: weights, identity, CSR ----
    const int NB = (NN + 1023) / 1024;   // 49
    wsplit_kernel<<<(10 * NP * KP + 255) / 256, 256>>>(W1, W2, wt);
    init_ident_kernel<<<2, 256>>>(ident);
    cudaMemsetAsync(cur, 0, NN * sizeof(int), 0);
    hist_kernel<<<(EE + 255) / 256, 256>>>(ei, cur);
    scan_sum_kernel<<<NB, 1024>>>(cur, bsum);
    scan_top_kernel<<<1, 64>>>(bsum, NB);
    scan_final_kernel<<<NB, 1024>>>(cur, bsum, rowptr);
    fill_kernel<<<(EE + 255) / 256, 256>>>(ei, cur, eidx);

    dim3 pg(NGR, 3);
    pool_kernel<<<pg, 128>>>(x, ident, ident + DD, 0, batch, pooled, counts);

    const float* hcur = x;
    const float* csc = ident;
    const float* csh = ident + DD;
    int crelu = 0;
    float* zb[2] = { bufA, bufB };
    const dim3 gemm_grid(NP / 64, (NN + 127) / 128);   // (5, 391)
    const int split_blocks = (NN * 80 + 255) / 256;
    const int agg_blocks = (NN * 32 + 255) / 256;

    for (int i = 0; i < LL; i++) {
        float* z = zb[i & 1];

        agg_split_kernel<<<agg_blocks, 256>>>(hcur, csc, csh, crelu, rowptr, eidx, h0);

        cudaMemsetAsync(stats, 0, 4 * DD * sizeof(float), 0);

        gemm_tc<<<gemm_grid, 256>>>(h0, wt + (size_t)i * NP * KP,
                                    b1 + i * DD, bufT, stats, stats + DD, NN);
        bn_prep_kernel<<<1, 320>>>(stats, stats + DD, g1 + i * DD, be1 + i * DD,
                                   stats + 4 * DD, stats + 5 * DD);
        bn_relu_split_kernel<<<split_blocks, 256>>>(bufT, stats + 4 * DD, stats + 5 * DD, h0);

        gemm_tc<<<gemm_grid, 256>>>(h0, wt + (size_t)(i + 5) * NP * KP,
                                    b2 + i * DD, z, stats + 2 * DD, stats + 3 * DD, NN);
        bn_prep_kernel<<<1, 320>>>(stats + 2 * DD, stats + 3 * DD, bng + i * DD, bnb + i * DD,
                                   stats + 6 * DD, stats + 7 * DD);

        pool_kernel<<<pg, 128>>>(z, stats + 6 * DD, stats + 7 * DD, 1, batch,
                                 pooled + (size_t)(i + 1) * NGR * DD, nullptr);

        hcur = z; csc = stats + 6 * DD; csh = stats + 7 * DD; crelu = 1;
    }

    head_kernel<<<NGR, CC>>>(pooled, counts, fcW, fcb, out);
}